// round 11
// baseline (speedup 1.0000x reference)
#include <cuda_runtime.h>
#include <math.h>
#include <stdint.h>

#define NN 50000
#define NE 800000
#define ETOT (NE + NN)
#define NEG 0.2f
#define EPSV 1e-16f
#define NB1 49   // ceil(NN/1024)
#define NCHUNK 4
#define RC 12544 // rows per chunk (98*128); last chunk = 12368

// ---------------- scratch (device globals; no allocation allowed) ----------
__device__ __align__(16) float g_mid[NN * 64];
__device__ __align__(16) float g_h0 [NN * 64];
__device__ __align__(16) float g_agg[NN * 256];
__device__ __align__(16) float g_o1 [NN * 256];
__device__ __align__(16) float g_h2 [NN * 64];
__device__ __align__(16) float g_o2 [NN * 64];
__device__ __align__(16) float g_as [NN * 4];
__device__ __align__(16) float g_ad [NN * 4];
__device__ __align__(16) float g_was[256];
__device__ __align__(16) float g_wad[256];
__device__ __align__(16) float g_aoff[8];
__device__ int g_deg[NN];
__device__ int g_off[NN + 1];
__device__ int g_srcs[ETOT];
__device__ int g_epos[ETOT];
__device__ int g_bsum[NB1];

// ---------------- CSR build ----------------
__global__ void k_count(const int* __restrict__ ei) {
    int i = blockIdx.x * blockDim.x + threadIdx.x;
    if (i >= ETOT) return;
    int d = (i < NE) ? ei[NE + i] : (i - NE);
    g_epos[i] = atomicAdd(&g_deg[d], 1);
}

__global__ void k_bsum() {
    __shared__ int sh[1024];
    int t = threadIdx.x;
    int i = blockIdx.x * 1024 + t;
    sh[t] = (i < NN) ? g_deg[i] : 0;
    __syncthreads();
#pragma unroll
    for (int o = 512; o > 0; o >>= 1) {
        if (t < o) sh[t] += sh[t + o];
        __syncthreads();
    }
    if (t == 0) g_bsum[blockIdx.x] = sh[0];
}

__global__ void k_swrite() {
    __shared__ int sh[1024];
    __shared__ int sb[64];
    __shared__ int sbase;
    int t = threadIdx.x;
    if (t < 64) sb[t] = (t < blockIdx.x && t < NB1) ? g_bsum[t] : 0;
    int i = blockIdx.x * 1024 + t;
    int v = (i < NN) ? g_deg[i] : 0;
    sh[t] = v;
    __syncthreads();
#pragma unroll
    for (int o = 1; o < 1024; o <<= 1) {
        int x = (t >= o) ? sh[t - o] : 0;
        __syncthreads();
        sh[t] += x;
        __syncthreads();
    }
    if (t == 0) {
        int b = 0;
#pragma unroll
        for (int j = 0; j < 64; j++) b += sb[j];
        sbase = b;
    }
    __syncthreads();
    int incl = sh[t];
    if (i < NN) {
        g_off[i] = sbase + incl - v;
        if (i == NN - 1) g_off[NN] = sbase + incl;
    }
}

__global__ void k_scatter(const int* __restrict__ ei) {
    int i = blockIdx.x * blockDim.x + threadIdx.x;
    if (i >= ETOT) return;
    int s, d;
    if (i < NE) { s = ei[i]; d = ei[NE + i]; }
    else        { s = i - NE; d = i - NE; }
    g_srcs[g_off[d] + g_epos[i]] = s;
}

// ---------------- encoder first layer (K=7) ----------------
__global__ void k_enc1(const float* __restrict__ x, const float* __restrict__ w1,
                       const float* __restrict__ b1) {
    int idx = blockIdx.x * blockDim.x + threadIdx.x;
    if (idx >= NN * 64) return;
    int n = idx >> 6, c = idx & 63;
    float s = b1[c];
#pragma unroll
    for (int k = 0; k < 7; k++) s += x[n * 7 + k] * w1[k * 64 + c];
    g_mid[idx] = fmaxf(s, 0.f);
}

// ---------------- tf32 tensor-core GEMM (3xTF32 split) ----------------
__device__ __forceinline__ float tf32_rn(float x) {
    uint32_t u;
    asm("cvt.rna.tf32.f32 %0, %1;" : "=r"(u) : "f"(x));
    return __uint_as_float(u);
}

__device__ __forceinline__ void mma_tf32(float4& d, const uint32_t a[4], const uint32_t b[2]) {
    asm volatile(
        "mma.sync.aligned.m16n8k8.row.col.f32.tf32.tf32.f32 "
        "{%0,%1,%2,%3},{%4,%5,%6,%7},{%8,%9},{%0,%1,%2,%3};\n"
        : "+f"(d.x), "+f"(d.y), "+f"(d.z), "+f"(d.w)
        : "r"(a[0]), "r"(a[1]), "r"(a[2]), "r"(a[3]), "r"(b[0]), "r"(b[1]));
}

// ACT: 0 none, 1 relu, 2 elu
// EPI: 0 normal store
//      1 store C AND compute layer-2 alphas from the 128x64 tile (axA=as, axB=ad)
//      2 decoder: relu tile, NO C store; out[r,0:4] = tile @ axA(64x4) + axB(4); axO=out
// mbase: row offset of this launch's chunk.
template <int ACT, int EPI>
__global__ void k_mma_gemm(const float* __restrict__ A, const float* __restrict__ B,
                           const float* __restrict__ bias, float* __restrict__ C,
                           int M, int K, int Nc, int lda, int ldb, int ldc, int zoff,
                           const float* __restrict__ axA, const float* __restrict__ axB,
                           float* __restrict__ axO, int mbase) {
    __shared__ __align__(16) float smbuf[8192];
    float (*Ah)[136] = (float(*)[136])(smbuf);
    float (*Al)[136] = (float(*)[136])(smbuf + 16 * 136);
    float (*Bh)[72]  = (float(*)[72]) (smbuf + 2 * 16 * 136);
    float (*Bl)[72]  = (float(*)[72]) (smbuf + 2 * 16 * 136 + 16 * 72);
    float* scratch   = smbuf;

    int zo = blockIdx.z * zoff;
    A += zo; B += zo;
    if (C) C += zo;
    if (bias) bias += zo;

    int tid  = threadIdx.x;
    int warp = tid >> 5, lane = tid & 31;
    int wm = warp >> 1, wn = warp & 1;
    int m0 = mbase + blockIdx.y * 128, n0 = blockIdx.x * 64;
    int grp = lane >> 2, tig = lane & 3;

    float4 acc[2][4];
#pragma unroll
    for (int i = 0; i < 2; i++)
#pragma unroll
        for (int j = 0; j < 4; j++) acc[i][j] = make_float4(0.f, 0.f, 0.f, 0.f);

    for (int k0 = 0; k0 < K; k0 += 16) {
#pragma unroll
        for (int r = 0; r < 2; r++) {
            int idx = tid + 256 * r;
            int m = idx >> 2, kq = idx & 3;
            int row = m0 + m;
            float4 v = make_float4(0.f, 0.f, 0.f, 0.f);
            if (row < M) v = *(const float4*)(A + (size_t)row * lda + k0 + 4 * kq);
            float h;
            h = tf32_rn(v.x); Ah[4*kq+0][m] = h; Al[4*kq+0][m] = tf32_rn(v.x - h);
            h = tf32_rn(v.y); Ah[4*kq+1][m] = h; Al[4*kq+1][m] = tf32_rn(v.y - h);
            h = tf32_rn(v.z); Ah[4*kq+2][m] = h; Al[4*kq+2][m] = tf32_rn(v.z - h);
            h = tf32_rn(v.w); Ah[4*kq+3][m] = h; Al[4*kq+3][m] = tf32_rn(v.w - h);
        }
        {
            int kk = tid >> 4, nq = tid & 15;
            float4 v = *(const float4*)(B + (size_t)(k0 + kk) * ldb + n0 + 4 * nq);
            float4 hv, lv;
            hv.x = tf32_rn(v.x); lv.x = tf32_rn(v.x - hv.x);
            hv.y = tf32_rn(v.y); lv.y = tf32_rn(v.y - hv.y);
            hv.z = tf32_rn(v.z); lv.z = tf32_rn(v.z - hv.z);
            hv.w = tf32_rn(v.w); lv.w = tf32_rn(v.w - hv.w);
            *(float4*)&Bh[kk][4 * nq] = hv;
            *(float4*)&Bl[kk][4 * nq] = lv;
        }
        __syncthreads();

#pragma unroll
        for (int ks = 0; ks < 2; ks++) {
            int kb = ks * 8;
            uint32_t aH[2][4], aL[2][4];
#pragma unroll
            for (int mt = 0; mt < 2; mt++) {
                int mb = wm * 32 + mt * 16 + grp;
                aH[mt][0] = __float_as_uint(Ah[kb + tig    ][mb]);
                aH[mt][1] = __float_as_uint(Ah[kb + tig    ][mb + 8]);
                aH[mt][2] = __float_as_uint(Ah[kb + tig + 4][mb]);
                aH[mt][3] = __float_as_uint(Ah[kb + tig + 4][mb + 8]);
                aL[mt][0] = __float_as_uint(Al[kb + tig    ][mb]);
                aL[mt][1] = __float_as_uint(Al[kb + tig    ][mb + 8]);
                aL[mt][2] = __float_as_uint(Al[kb + tig + 4][mb]);
                aL[mt][3] = __float_as_uint(Al[kb + tig + 4][mb + 8]);
            }
#pragma unroll
            for (int nt = 0; nt < 4; nt++) {
                int nb = wn * 32 + nt * 8 + grp;
                uint32_t bH[2], bL[2];
                bH[0] = __float_as_uint(Bh[kb + tig    ][nb]);
                bH[1] = __float_as_uint(Bh[kb + tig + 4][nb]);
                bL[0] = __float_as_uint(Bl[kb + tig    ][nb]);
                bL[1] = __float_as_uint(Bl[kb + tig + 4][nb]);
#pragma unroll
                for (int mt = 0; mt < 2; mt++) {
                    mma_tf32(acc[mt][nt], aH[mt], bH);
                    mma_tf32(acc[mt][nt], aL[mt], bH);
                    mma_tf32(acc[mt][nt], aH[mt], bL);
                }
            }
        }
        __syncthreads();
    }

#pragma unroll
    for (int mt = 0; mt < 2; mt++) {
#pragma unroll
        for (int nt = 0; nt < 4; nt++) {
            int lc  = wn * 32 + nt * 8 + 2 * tig;
            int col = n0 + lc;
            float b0 = bias ? bias[col] : 0.f;
            float b1 = bias ? bias[col + 1] : 0.f;
            int lr  = wm * 32 + mt * 16 + grp;
            int rt_ = m0 + lr;
            float2 v0 = make_float2(acc[mt][nt].x + b0, acc[mt][nt].y + b1);
            float2 v1 = make_float2(acc[mt][nt].z + b0, acc[mt][nt].w + b1);
            if (ACT == 1) {
                v0.x = fmaxf(v0.x, 0.f); v0.y = fmaxf(v0.y, 0.f);
                v1.x = fmaxf(v1.x, 0.f); v1.y = fmaxf(v1.y, 0.f);
            } else if (ACT == 2) {
                v0.x = v0.x > 0.f ? v0.x : expm1f(v0.x);
                v0.y = v0.y > 0.f ? v0.y : expm1f(v0.y);
                v1.x = v1.x > 0.f ? v1.x : expm1f(v1.x);
                v1.y = v1.y > 0.f ? v1.y : expm1f(v1.y);
            }
            if (EPI != 2) {
                if (rt_ < M)     *(float2*)(C + (size_t)rt_ * ldc + col)       = v0;
                if (rt_ + 8 < M) *(float2*)(C + (size_t)(rt_ + 8) * ldc + col) = v1;
            }
            if (EPI != 0) {
                scratch[lr * 64 + lc]           = v0.x;
                scratch[lr * 64 + lc + 1]       = v0.y;
                scratch[(lr + 8) * 64 + lc]     = v1.x;
                scratch[(lr + 8) * 64 + lc + 1] = v1.y;
            }
        }
    }

    if (EPI == 1) {   // fused layer-2 alpha
        __syncthreads();
        float a0 = axA[2 * lane], a1 = axA[2 * lane + 1];
        float d0 = axB[2 * lane], d1 = axB[2 * lane + 1];
        int h = lane >> 3;
#pragma unroll 4
        for (int r = warp * 16; r < warp * 16 + 16; r++) {
            float u0 = scratch[r * 64 + 2 * lane];
            float u1 = scratch[r * 64 + 2 * lane + 1];
            float s  = u0 * a0 + u1 * a1;
            float dd = u0 * d0 + u1 * d1;
#pragma unroll
            for (int o = 4; o; o >>= 1) {
                s  += __shfl_xor_sync(0xffffffffu, s,  o);
                dd += __shfl_xor_sync(0xffffffffu, dd, o);
            }
            int grow = m0 + r;
            if ((lane & 7) == 0 && grow < M) {
                g_as[grow * 4 + h] = s;
                g_ad[grow * 4 + h] = dd;
            }
        }
    } else if (EPI == 2) {  // fused decoder tail
        __syncthreads();
        float4 wa = ((const float4*)axA)[2 * lane];
        float4 wb = ((const float4*)axA)[2 * lane + 1];
        float4 bb = *(const float4*)axB;
#pragma unroll 4
        for (int r = warp * 16; r < warp * 16 + 16; r++) {
            float u0 = scratch[r * 64 + 2 * lane];
            float u1 = scratch[r * 64 + 2 * lane + 1];
            float4 o;
            o.x = u0 * wa.x + u1 * wb.x;
            o.y = u0 * wa.y + u1 * wb.y;
            o.z = u0 * wa.z + u1 * wb.z;
            o.w = u0 * wa.w + u1 * wb.w;
#pragma unroll
            for (int of = 16; of; of >>= 1) {
                o.x += __shfl_xor_sync(0xffffffffu, o.x, of);
                o.y += __shfl_xor_sync(0xffffffffu, o.y, of);
                o.z += __shfl_xor_sync(0xffffffffu, o.z, of);
                o.w += __shfl_xor_sync(0xffffffffu, o.w, of);
            }
            int grow = m0 + r;
            if (lane == 0 && grow < M) {
                ((float4*)axO)[grow] = make_float4(o.x + bb.x, o.y + bb.y,
                                                   o.z + bb.z, o.w + bb.w);
            }
        }
    }
}

// ---------------- double fold: alpha1 directly from g_mid -----------------
__global__ void k_fold1b(const float* __restrict__ w, const float* __restrict__ as_,
                         const float* __restrict__ ad_, const float* __restrict__ w2,
                         const float* __restrict__ b2) {
    __shared__ float sw[64][4], sd[64][4];
    int t = threadIdx.x;          // t = k*4 + h
    int k = t >> 2, h = t & 3;
    float s = 0.f, d = 0.f;
#pragma unroll
    for (int c = 0; c < 64; c++) {
        float v = w[k * 256 + h * 64 + c];
        s += v * as_[h * 64 + c];
        d += v * ad_[h * 64 + c];
    }
    sw[k][h] = s;
    sd[k][h] = d;
    __syncthreads();
    float s2 = 0.f, d2 = 0.f;
#pragma unroll
    for (int o = 0; o < 64; o++) {
        float v = w2[k * 64 + o];
        s2 += v * sw[o][h];
        d2 += v * sd[o][h];
    }
    g_was[t] = s2;
    g_wad[t] = d2;
    if (t < 8) {
        int hh = t & 3;
        float acc = 0.f;
#pragma unroll
        for (int o = 0; o < 64; o++)
            acc += b2[o] * (t >= 4 ? sd[o][hh] : sw[o][hh]);
        g_aoff[t] = acc;
    }
}

// ---------------- alpha for layer 1: from g_mid via double-folded weights -
__global__ void k_alpha1(const float* __restrict__ midf) {
    int warp = (blockIdx.x * blockDim.x + threadIdx.x) >> 5;
    int lane = threadIdx.x & 31;
    if (warp >= NN) return;
    float v1 = midf[(size_t)warp * 64 + lane];
    float v2 = midf[(size_t)warp * 64 + lane + 32];
    float4 wsA = ((const float4*)g_was)[lane];
    float4 wsB = ((const float4*)g_was)[lane + 32];
    float4 wdA = ((const float4*)g_wad)[lane];
    float4 wdB = ((const float4*)g_wad)[lane + 32];
    float4 ps, pd;
    ps.x = v1 * wsA.x + v2 * wsB.x; ps.y = v1 * wsA.y + v2 * wsB.y;
    ps.z = v1 * wsA.z + v2 * wsB.z; ps.w = v1 * wsA.w + v2 * wsB.w;
    pd.x = v1 * wdA.x + v2 * wdB.x; pd.y = v1 * wdA.y + v2 * wdB.y;
    pd.z = v1 * wdA.z + v2 * wdB.z; pd.w = v1 * wdA.w + v2 * wdB.w;
#pragma unroll
    for (int o = 16; o; o >>= 1) {
        ps.x += __shfl_xor_sync(0xffffffffu, ps.x, o);
        ps.y += __shfl_xor_sync(0xffffffffu, ps.y, o);
        ps.z += __shfl_xor_sync(0xffffffffu, ps.z, o);
        ps.w += __shfl_xor_sync(0xffffffffu, ps.w, o);
        pd.x += __shfl_xor_sync(0xffffffffu, pd.x, o);
        pd.y += __shfl_xor_sync(0xffffffffu, pd.y, o);
        pd.z += __shfl_xor_sync(0xffffffffu, pd.z, o);
        pd.w += __shfl_xor_sync(0xffffffffu, pd.w, o);
    }
    if (lane == 0) {
        float4 os = ((const float4*)g_aoff)[0];
        float4 od = ((const float4*)g_aoff)[1];
        ps.x += os.x; ps.y += os.y; ps.z += os.z; ps.w += os.w;
        pd.x += od.x; pd.y += od.y; pd.z += od.z; pd.w += od.w;
        ((float4*)g_as)[warp] = ps;
        ((float4*)g_ad)[warp] = pd;
    }
}

__device__ __forceinline__ float lrelu(float e) { return e > 0.f ? e : NEG * e; }

// ---------------- layer-1 aggregate, half-warp edge-split, chunked --------
__global__ void k_agg1(const float* __restrict__ h0f, float* __restrict__ aggout,
                       int nbase, int ncnt) {
    __shared__ float4 sh_w[8][32];
    __shared__ int    sh_s[8][32];
    int wl = (blockIdx.x * blockDim.x + threadIdx.x) >> 5;
    int lane = threadIdx.x & 31;
    if (wl >= ncnt) return;
    int wip = threadIdx.x >> 5;
    int half = lane >> 4, sub = lane & 15;
    int d = nbase + wl;
    int r0 = g_off[d], deg = g_off[d + 1] - r0;
    float4 adv = ((const float4*)g_ad)[d];

    float4 A0 = make_float4(0.f,0.f,0.f,0.f), A1 = A0, A2 = A0, A3 = A0;
    float s0 = 0.f, s1 = 0.f, s2 = 0.f, s3 = 0.f;

    for (int base = 0; base < deg; base += 32) {
        int n = deg - base; if (n > 32) n = 32;
        float4 w = make_float4(0.f, 0.f, 0.f, 0.f); int s = 0;
        if (lane < n) {
            s = g_srcs[r0 + base + lane];
            float4 a = ((const float4*)g_as)[s];
            w.x = __expf(lrelu(a.x + adv.x));
            w.y = __expf(lrelu(a.y + adv.y));
            w.z = __expf(lrelu(a.z + adv.z));
            w.w = __expf(lrelu(a.w + adv.w));
        }
        s0 += w.x; s1 += w.y; s2 += w.z; s3 += w.w;
        sh_w[wip][lane] = w;
        sh_s[wip][lane] = s;
        __syncwarp();
#pragma unroll 4
        for (int j = half; j < n; j += 2) {
            float4 wv = sh_w[wip][j];
            int sj = sh_s[wip][j];
            float4 v = *(const float4*)(h0f + (size_t)sj * 64 + sub * 4);
            A0.x += v.x*wv.x; A0.y += v.y*wv.x; A0.z += v.z*wv.x; A0.w += v.w*wv.x;
            A1.x += v.x*wv.y; A1.y += v.y*wv.y; A1.z += v.z*wv.y; A1.w += v.w*wv.y;
            A2.x += v.x*wv.z; A2.y += v.y*wv.z; A2.z += v.z*wv.z; A2.w += v.w*wv.z;
            A3.x += v.x*wv.w; A3.y += v.y*wv.w; A3.z += v.z*wv.w; A3.w += v.w*wv.w;
        }
        __syncwarp();
    }
    A0.x += __shfl_xor_sync(0xffffffffu, A0.x, 16);
    A0.y += __shfl_xor_sync(0xffffffffu, A0.y, 16);
    A0.z += __shfl_xor_sync(0xffffffffu, A0.z, 16);
    A0.w += __shfl_xor_sync(0xffffffffu, A0.w, 16);
    A1.x += __shfl_xor_sync(0xffffffffu, A1.x, 16);
    A1.y += __shfl_xor_sync(0xffffffffu, A1.y, 16);
    A1.z += __shfl_xor_sync(0xffffffffu, A1.z, 16);
    A1.w += __shfl_xor_sync(0xffffffffu, A1.w, 16);
    A2.x += __shfl_xor_sync(0xffffffffu, A2.x, 16);
    A2.y += __shfl_xor_sync(0xffffffffu, A2.y, 16);
    A2.z += __shfl_xor_sync(0xffffffffu, A2.z, 16);
    A2.w += __shfl_xor_sync(0xffffffffu, A2.w, 16);
    A3.x += __shfl_xor_sync(0xffffffffu, A3.x, 16);
    A3.y += __shfl_xor_sync(0xffffffffu, A3.y, 16);
    A3.z += __shfl_xor_sync(0xffffffffu, A3.z, 16);
    A3.w += __shfl_xor_sync(0xffffffffu, A3.w, 16);
#pragma unroll
    for (int o = 16; o; o >>= 1) {
        s0 += __shfl_xor_sync(0xffffffffu, s0, o);
        s1 += __shfl_xor_sync(0xffffffffu, s1, o);
        s2 += __shfl_xor_sync(0xffffffffu, s2, o);
        s3 += __shfl_xor_sync(0xffffffffu, s3, o);
    }
    float i0 = 1.f / (s0 + EPSV), i1 = 1.f / (s1 + EPSV);
    float i2 = 1.f / (s2 + EPSV), i3 = 1.f / (s3 + EPSV);
    float* ob = aggout + (size_t)d * 256 + sub * 4;
    if (half == 0) {
        *(float4*)(ob)      = make_float4(A0.x*i0, A0.y*i0, A0.z*i0, A0.w*i0);
        *(float4*)(ob + 64) = make_float4(A1.x*i1, A1.y*i1, A1.z*i1, A1.w*i1);
    } else {
        *(float4*)(ob + 128) = make_float4(A2.x*i2, A2.y*i2, A2.z*i2, A2.w*i2);
        *(float4*)(ob + 192) = make_float4(A3.x*i3, A3.y*i3, A3.z*i3, A3.w*i3);
    }
}

// ---------------- layer-2 aggregate, half-warp edge-split, chunked --------
__global__ void k_agg2(const float* __restrict__ hfeat, const float* __restrict__ bias,
                       float* __restrict__ out, int nbase, int ncnt) {
    __shared__ float4 sh_w[8][32];
    __shared__ int    sh_s[8][32];
    int wl = (blockIdx.x * blockDim.x + threadIdx.x) >> 5;
    int lane = threadIdx.x & 31;
    if (wl >= ncnt) return;
    int wip = threadIdx.x >> 5;
    int half = lane >> 4, sub = lane & 15;
    int headq = sub >> 2;
    int d = nbase + wl;
    int r0 = g_off[d], deg = g_off[d + 1] - r0;
    float4 adv = ((const float4*)g_ad)[d];

    float4 acc = make_float4(0.f, 0.f, 0.f, 0.f);
    float s0 = 0.f, s1 = 0.f, s2 = 0.f, s3 = 0.f;
    for (int base = 0; base < deg; base += 32) {
        int n = deg - base; if (n > 32) n = 32;
        float4 w = make_float4(0.f, 0.f, 0.f, 0.f); int s = 0;
        if (lane < n) {
            s = g_srcs[r0 + base + lane];
            float4 a = ((const float4*)g_as)[s];
            w.x = __expf(lrelu(a.x + adv.x));
            w.y = __expf(lrelu(a.y + adv.y));
            w.z = __expf(lrelu(a.z + adv.z));
            w.w = __expf(lrelu(a.w + adv.w));
        }
        s0 += w.x; s1 += w.y; s2 += w.z; s3 += w.w;
        sh_w[wip][lane] = w;
        sh_s[wip][lane] = s;
        __syncwarp();
#pragma unroll 4
        for (int j = half; j < n; j += 2) {
            float4 wv = sh_w[wip][j];
            int sj = sh_s[wip][j];
            float wm = headq == 0 ? wv.x : headq == 1 ? wv.y : headq == 2 ? wv.z : wv.w;
            float4 v = *(const float4*)(hfeat + (size_t)sj * 64 + sub * 4);
            acc.x += v.x * wm; acc.y += v.y * wm;
            acc.z += v.z * wm; acc.w += v.w * wm;
        }
        __syncwarp();
    }
    acc.x += __shfl_xor_sync(0xffffffffu, acc.x, 16);
    acc.y += __shfl_xor_sync(0xffffffffu, acc.y, 16);
    acc.z += __shfl_xor_sync(0xffffffffu, acc.z, 16);
    acc.w += __shfl_xor_sync(0xffffffffu, acc.w, 16);
#pragma unroll
    for (int o = 16; o; o >>= 1) {
        s0 += __shfl_xor_sync(0xffffffffu, s0, o);
        s1 += __shfl_xor_sync(0xffffffffu, s1, o);
        s2 += __shfl_xor_sync(0xffffffffu, s2, o);
        s3 += __shfl_xor_sync(0xffffffffu, s3, o);
    }
    if (half == 0) {
        float im = headq == 0 ? 1.f / (s0 + EPSV) : headq == 1 ? 1.f / (s1 + EPSV)
                 : headq == 2 ? 1.f / (s2 + EPSV) : 1.f / (s3 + EPSV);
        float4 bv = ((const float4*)bias)[sub];
        float4 r;
        r.x = acc.x * im + bv.x;
        r.y = acc.y * im + bv.y;
        r.z = acc.z * im + bv.z;
        r.w = acc.w * im + bv.w;
        ((float4*)(out + (size_t)d * 64))[sub] = r;
    }
}

// ---------------- launch ----------------
extern "C" void kernel_launch(void* const* d_in, const int* in_sizes, int n_in,
                              void* d_out, int out_size) {
    const float* x      = (const float*)d_in[0];
    const int*   ei     = (const int*)  d_in[1];
    const float* enc_w1 = (const float*)d_in[2];
    const float* enc_b1 = (const float*)d_in[3];
    const float* enc_w2 = (const float*)d_in[4];
    const float* enc_b2 = (const float*)d_in[5];
    const float* g1_w   = (const float*)d_in[6];
    const float* g1_as  = (const float*)d_in[7];
    const float* g1_ad  = (const float*)d_in[8];
    const float* g1_b   = (const float*)d_in[9];
    const float* g2_w   = (const float*)d_in[10];
    const float* g2_as  = (const float*)d_in[11];
    const float* g2_ad  = (const float*)d_in[12];
    const float* g2_b   = (const float*)d_in[13];
    const float* dec_w1 = (const float*)d_in[14];
    const float* dec_b1 = (const float*)d_in[15];
    const float* dec_w2 = (const float*)d_in[16];
    const float* dec_b2 = (const float*)d_in[17];
    float* out = (float*)d_out;

    float *mid, *h0, *agg, *o1, *h2, *o2;
    cudaGetSymbolAddress((void**)&mid, g_mid);
    cudaGetSymbolAddress((void**)&h0,  g_h0);
    cudaGetSymbolAddress((void**)&agg, g_agg);
    cudaGetSymbolAddress((void**)&o1,  g_o1);
    cudaGetSymbolAddress((void**)&h2,  g_h2);
    cudaGetSymbolAddress((void**)&o2,  g_o2);
    void* degp;
    cudaGetSymbolAddress(&degp, g_deg);

    static cudaStream_t s1 = 0, s2 = 0;
    static cudaEvent_t evRoot = 0, evCSR = 0, evMid = 0, evH0 = 0, evG2 = 0;
    static cudaEvent_t evA1[NCHUNK], evA2[NCHUNK];
    static int inited = 0;
    if (!inited) {
        cudaStreamCreateWithFlags(&s1, cudaStreamNonBlocking);
        cudaStreamCreateWithFlags(&s2, cudaStreamNonBlocking);
        cudaEventCreateWithFlags(&evRoot, cudaEventDisableTiming);
        cudaEventCreateWithFlags(&evCSR,  cudaEventDisableTiming);
        cudaEventCreateWithFlags(&evMid,  cudaEventDisableTiming);
        cudaEventCreateWithFlags(&evH0,   cudaEventDisableTiming);
        cudaEventCreateWithFlags(&evG2,   cudaEventDisableTiming);
        for (int i = 0; i < NCHUNK; i++) {
            cudaEventCreateWithFlags(&evA1[i], cudaEventDisableTiming);
            cudaEventCreateWithFlags(&evA2[i], cudaEventDisableTiming);
        }
        inited = 1;
    }

    const int WPB = 6250;      // 50000 warps / 8 warps-per-block

    // chunk geometry
    int cbase[NCHUNK], ccnt[NCHUNK];
    for (int i = 0; i < NCHUNK; i++) {
        cbase[i] = i * RC;
        ccnt[i]  = (i == NCHUNK - 1) ? (NN - (NCHUNK - 1) * RC) : RC;
    }

    // ---- fork ----
    cudaEventRecord(evRoot, 0);
    cudaStreamWaitEvent(s1, evRoot, 0);
    cudaStreamWaitEvent(s2, evRoot, 0);

    // branch s1: CSR build
    cudaMemsetAsync(degp, 0, NN * sizeof(int), s1);
    k_count<<<(ETOT + 255) / 256, 256, 0, s1>>>(ei);
    k_bsum<<<NB1, 1024, 0, s1>>>();
    k_swrite<<<NB1, 1024, 0, s1>>>();
    k_scatter<<<(ETOT + 255) / 256, 256, 0, s1>>>(ei);
    cudaEventRecord(evCSR, s1);

    // branch s2: double-fold, then alpha1 from mid
    k_fold1b<<<1, 256, 0, s2>>>(g1_w, g1_as, g1_ad, enc_w2, enc_b2);

    // main: encoder
    k_enc1<<<(NN * 64 + 255) / 256, 256>>>(x, enc_w1, enc_b1);
    cudaEventRecord(evMid, 0);
    cudaStreamWaitEvent(s2, evMid, 0);
    k_alpha1<<<WPB, 256, 0, s2>>>(mid);

    k_mma_gemm<0, 0><<<dim3(1, (NN + 127) / 128), 256>>>(mid, enc_w2, enc_b2, h0,
                                           NN, 64, 64, 64, 64, 64, 0,
                                           nullptr, nullptr, nullptr, 0);
    cudaEventRecord(evH0, 0);

    // ---- pipelined middle: agg1 chunks on s2, GEMM chunks trail on main ----
    cudaStreamWaitEvent(s2, evCSR, 0);
    cudaStreamWaitEvent(s2, evH0, 0);
    for (int i = 0; i < NCHUNK; i++) {
        k_agg1<<<(ccnt[i] + 7) / 8, 256, 0, s2>>>(h0, agg, cbase[i], ccnt[i]);
        cudaEventRecord(evA1[i], s2);
    }
    for (int i = 0; i < NCHUNK; i++) {
        int gyc = (ccnt[i] + 127) / 128;
        cudaStreamWaitEvent(0, evA1[i], 0);
        // layer-1 per-head GEMM (+bias, ELU) for this row chunk
        k_mma_gemm<2, 0><<<dim3(1, gyc, 4), 256>>>(agg, g1_w, g1_b, o1,
                                                   NN, 64, 64, 256, 256, 256, 64,
                                                   nullptr, nullptr, nullptr, cbase[i]);
        // layer-2 weight GEMM with fused alpha2 epilogue for this row chunk
        k_mma_gemm<0, 1><<<dim3(1, gyc), 256>>>(o1, g2_w, nullptr, h2,
                                                NN, 256, 64, 256, 64, 64, 0,
                                                g2_as, g2_ad, nullptr, cbase[i]);
    }
    cudaEventRecord(evG2, 0);

    // ---- agg2 chunks on s2 (need ALL h2 + alphas), decoder chunks trail ----
    cudaStreamWaitEvent(s2, evG2, 0);
    for (int i = 0; i < NCHUNK; i++) {
        k_agg2<<<(ccnt[i] + 7) / 8, 256, 0, s2>>>(h2, g2_b, o2, cbase[i], ccnt[i]);
        cudaEventRecord(evA2[i], s2);
    }
    for (int i = 0; i < NCHUNK; i++) {
        int gyc = (ccnt[i] + 127) / 128;
        cudaStreamWaitEvent(0, evA2[i], 0);
        k_mma_gemm<1, 2><<<dim3(1, gyc), 256>>>(o2, dec_w1, dec_b1, nullptr,
                                                NN, 64, 64, 64, 64, 64, 0,
                                                dec_w2, dec_b2, out, cbase[i]);
    }
}

// round 12
// speedup vs baseline: 1.2324x; 1.2324x over previous
#include <cuda_runtime.h>
#include <math.h>
#include <stdint.h>

#define NN 50000
#define NE 800000
#define ETOT (NE + NN)
#define NEG 0.2f
#define EPSV 1e-16f
#define NB1 49   // ceil(NN/1024)

// ---------------- scratch (device globals; no allocation allowed) ----------
__device__ __align__(16) float g_mid[NN * 64];
__device__ __align__(16) float g_h0 [NN * 64];
__device__ __align__(16) float g_agg[NN * 256];
__device__ __align__(16) float g_o1 [NN * 256];
__device__ __align__(16) float g_h2 [NN * 64];
__device__ __align__(16) float g_o2 [NN * 64];
__device__ __align__(16) float g_as [NN * 4];
__device__ __align__(16) float g_ad [NN * 4];
__device__ __align__(16) float g_was[256];
__device__ __align__(16) float g_wad[256];
__device__ __align__(16) float g_aoff[8];
__device__ int g_deg[NN];
__device__ int g_off[NN + 1];
__device__ int g_srcs[ETOT];
__device__ int g_epos[ETOT];
__device__ int g_bsum[NB1];

// ---------------- CSR build ----------------
__global__ void k_count(const int* __restrict__ ei) {
    int i = blockIdx.x * blockDim.x + threadIdx.x;
    if (i >= ETOT) return;
    int d = (i < NE) ? ei[NE + i] : (i - NE);
    g_epos[i] = atomicAdd(&g_deg[d], 1);
}

__global__ void k_bsum() {
    __shared__ int sh[1024];
    int t = threadIdx.x;
    int i = blockIdx.x * 1024 + t;
    sh[t] = (i < NN) ? g_deg[i] : 0;
    __syncthreads();
#pragma unroll
    for (int o = 512; o > 0; o >>= 1) {
        if (t < o) sh[t] += sh[t + o];
        __syncthreads();
    }
    if (t == 0) g_bsum[blockIdx.x] = sh[0];
}

__global__ void k_swrite() {
    __shared__ int sh[1024];
    __shared__ int sb[64];
    __shared__ int sbase;
    int t = threadIdx.x;
    if (t < 64) sb[t] = (t < blockIdx.x && t < NB1) ? g_bsum[t] : 0;
    int i = blockIdx.x * 1024 + t;
    int v = (i < NN) ? g_deg[i] : 0;
    sh[t] = v;
    __syncthreads();
#pragma unroll
    for (int o = 1; o < 1024; o <<= 1) {
        int x = (t >= o) ? sh[t - o] : 0;
        __syncthreads();
        sh[t] += x;
        __syncthreads();
    }
    if (t == 0) {
        int b = 0;
#pragma unroll
        for (int j = 0; j < 64; j++) b += sb[j];
        sbase = b;
    }
    __syncthreads();
    int incl = sh[t];
    if (i < NN) {
        g_off[i] = sbase + incl - v;
        if (i == NN - 1) g_off[NN] = sbase + incl;
    }
}

__global__ void k_scatter(const int* __restrict__ ei) {
    int i = blockIdx.x * blockDim.x + threadIdx.x;
    if (i >= ETOT) return;
    int s, d;
    if (i < NE) { s = ei[i]; d = ei[NE + i]; }
    else        { s = i - NE; d = i - NE; }
    g_srcs[g_off[d] + g_epos[i]] = s;
}

// ---------------- encoder first layer (K=7) ----------------
__global__ void k_enc1(const float* __restrict__ x, const float* __restrict__ w1,
                       const float* __restrict__ b1) {
    int idx = blockIdx.x * blockDim.x + threadIdx.x;
    if (idx >= NN * 64) return;
    int n = idx >> 6, c = idx & 63;
    float s = b1[c];
#pragma unroll
    for (int k = 0; k < 7; k++) s += x[n * 7 + k] * w1[k * 64 + c];
    g_mid[idx] = fmaxf(s, 0.f);
}

// ---------------- tf32 tensor-core GEMM (3xTF32 split) ----------------
__device__ __forceinline__ float tf32_rn(float x) {
    uint32_t u;
    asm("cvt.rna.tf32.f32 %0, %1;" : "=r"(u) : "f"(x));
    return __uint_as_float(u);
}

__device__ __forceinline__ void mma_tf32(float4& d, const uint32_t a[4], const uint32_t b[2]) {
    asm volatile(
        "mma.sync.aligned.m16n8k8.row.col.f32.tf32.tf32.f32 "
        "{%0,%1,%2,%3},{%4,%5,%6,%7},{%8,%9},{%0,%1,%2,%3};\n"
        : "+f"(d.x), "+f"(d.y), "+f"(d.z), "+f"(d.w)
        : "r"(a[0]), "r"(a[1]), "r"(a[2]), "r"(a[3]), "r"(b[0]), "r"(b[1]));
}

// ACT: 0 none, 1 relu, 2 elu
// EPI: 0 normal store
//      1 store C AND compute layer-2 alphas from the 128x64 tile (axA=as, axB=ad)
//      2 decoder: relu tile, NO C store; out[r,0:4] = tile @ axA(64x4) + axB(4); axO=out
template <int ACT, int EPI>
__global__ void k_mma_gemm(const float* __restrict__ A, const float* __restrict__ B,
                           const float* __restrict__ bias, float* __restrict__ C,
                           int M, int K, int Nc, int lda, int ldb, int ldc, int zoff,
                           const float* __restrict__ axA, const float* __restrict__ axB,
                           float* __restrict__ axO) {
    __shared__ __align__(16) float smbuf[8192];
    float (*Ah)[136] = (float(*)[136])(smbuf);
    float (*Al)[136] = (float(*)[136])(smbuf + 16 * 136);
    float (*Bh)[72]  = (float(*)[72]) (smbuf + 2 * 16 * 136);
    float (*Bl)[72]  = (float(*)[72]) (smbuf + 2 * 16 * 136 + 16 * 72);
    float* scratch   = smbuf;

    int zo = blockIdx.z * zoff;
    A += zo; B += zo;
    if (C) C += zo;
    if (bias) bias += zo;

    int tid  = threadIdx.x;
    int warp = tid >> 5, lane = tid & 31;
    int wm = warp >> 1, wn = warp & 1;
    int m0 = blockIdx.y * 128, n0 = blockIdx.x * 64;
    int grp = lane >> 2, tig = lane & 3;

    float4 acc[2][4];
#pragma unroll
    for (int i = 0; i < 2; i++)
#pragma unroll
        for (int j = 0; j < 4; j++) acc[i][j] = make_float4(0.f, 0.f, 0.f, 0.f);

    for (int k0 = 0; k0 < K; k0 += 16) {
#pragma unroll
        for (int r = 0; r < 2; r++) {
            int idx = tid + 256 * r;
            int m = idx >> 2, kq = idx & 3;
            int row = m0 + m;
            float4 v = make_float4(0.f, 0.f, 0.f, 0.f);
            if (row < M) v = *(const float4*)(A + (size_t)row * lda + k0 + 4 * kq);
            float h;
            h = tf32_rn(v.x); Ah[4*kq+0][m] = h; Al[4*kq+0][m] = tf32_rn(v.x - h);
            h = tf32_rn(v.y); Ah[4*kq+1][m] = h; Al[4*kq+1][m] = tf32_rn(v.y - h);
            h = tf32_rn(v.z); Ah[4*kq+2][m] = h; Al[4*kq+2][m] = tf32_rn(v.z - h);
            h = tf32_rn(v.w); Ah[4*kq+3][m] = h; Al[4*kq+3][m] = tf32_rn(v.w - h);
        }
        {
            int kk = tid >> 4, nq = tid & 15;
            float4 v = *(const float4*)(B + (size_t)(k0 + kk) * ldb + n0 + 4 * nq);
            float4 hv, lv;
            hv.x = tf32_rn(v.x); lv.x = tf32_rn(v.x - hv.x);
            hv.y = tf32_rn(v.y); lv.y = tf32_rn(v.y - hv.y);
            hv.z = tf32_rn(v.z); lv.z = tf32_rn(v.z - hv.z);
            hv.w = tf32_rn(v.w); lv.w = tf32_rn(v.w - hv.w);
            *(float4*)&Bh[kk][4 * nq] = hv;
            *(float4*)&Bl[kk][4 * nq] = lv;
        }
        __syncthreads();

#pragma unroll
        for (int ks = 0; ks < 2; ks++) {
            int kb = ks * 8;
            uint32_t aH[2][4], aL[2][4];
#pragma unroll
            for (int mt = 0; mt < 2; mt++) {
                int mb = wm * 32 + mt * 16 + grp;
                aH[mt][0] = __float_as_uint(Ah[kb + tig    ][mb]);
                aH[mt][1] = __float_as_uint(Ah[kb + tig    ][mb + 8]);
                aH[mt][2] = __float_as_uint(Ah[kb + tig + 4][mb]);
                aH[mt][3] = __float_as_uint(Ah[kb + tig + 4][mb + 8]);
                aL[mt][0] = __float_as_uint(Al[kb + tig    ][mb]);
                aL[mt][1] = __float_as_uint(Al[kb + tig    ][mb + 8]);
                aL[mt][2] = __float_as_uint(Al[kb + tig + 4][mb]);
                aL[mt][3] = __float_as_uint(Al[kb + tig + 4][mb + 8]);
            }
#pragma unroll
            for (int nt = 0; nt < 4; nt++) {
                int nb = wn * 32 + nt * 8 + grp;
                uint32_t bH[2], bL[2];
                bH[0] = __float_as_uint(Bh[kb + tig    ][nb]);
                bH[1] = __float_as_uint(Bh[kb + tig + 4][nb]);
                bL[0] = __float_as_uint(Bl[kb + tig    ][nb]);
                bL[1] = __float_as_uint(Bl[kb + tig + 4][nb]);
#pragma unroll
                for (int mt = 0; mt < 2; mt++) {
                    mma_tf32(acc[mt][nt], aH[mt], bH);
                    mma_tf32(acc[mt][nt], aL[mt], bH);
                    mma_tf32(acc[mt][nt], aH[mt], bL);
                }
            }
        }
        __syncthreads();
    }

#pragma unroll
    for (int mt = 0; mt < 2; mt++) {
#pragma unroll
        for (int nt = 0; nt < 4; nt++) {
            int lc  = wn * 32 + nt * 8 + 2 * tig;
            int col = n0 + lc;
            float b0 = bias ? bias[col] : 0.f;
            float b1 = bias ? bias[col + 1] : 0.f;
            int lr  = wm * 32 + mt * 16 + grp;
            int rt_ = m0 + lr;
            float2 v0 = make_float2(acc[mt][nt].x + b0, acc[mt][nt].y + b1);
            float2 v1 = make_float2(acc[mt][nt].z + b0, acc[mt][nt].w + b1);
            if (ACT == 1) {
                v0.x = fmaxf(v0.x, 0.f); v0.y = fmaxf(v0.y, 0.f);
                v1.x = fmaxf(v1.x, 0.f); v1.y = fmaxf(v1.y, 0.f);
            } else if (ACT == 2) {
                v0.x = v0.x > 0.f ? v0.x : expm1f(v0.x);
                v0.y = v0.y > 0.f ? v0.y : expm1f(v0.y);
                v1.x = v1.x > 0.f ? v1.x : expm1f(v1.x);
                v1.y = v1.y > 0.f ? v1.y : expm1f(v1.y);
            }
            if (EPI != 2) {
                if (rt_ < M)     *(float2*)(C + (size_t)rt_ * ldc + col)       = v0;
                if (rt_ + 8 < M) *(float2*)(C + (size_t)(rt_ + 8) * ldc + col) = v1;
            }
            if (EPI != 0) {
                scratch[lr * 64 + lc]           = v0.x;
                scratch[lr * 64 + lc + 1]       = v0.y;
                scratch[(lr + 8) * 64 + lc]     = v1.x;
                scratch[(lr + 8) * 64 + lc + 1] = v1.y;
            }
        }
    }

    if (EPI == 1) {   // fused layer-2 alpha
        __syncthreads();
        float a0 = axA[2 * lane], a1 = axA[2 * lane + 1];
        float d0 = axB[2 * lane], d1 = axB[2 * lane + 1];
        int h = lane >> 3;
#pragma unroll 4
        for (int r = warp * 16; r < warp * 16 + 16; r++) {
            float u0 = scratch[r * 64 + 2 * lane];
            float u1 = scratch[r * 64 + 2 * lane + 1];
            float s  = u0 * a0 + u1 * a1;
            float dd = u0 * d0 + u1 * d1;
#pragma unroll
            for (int o = 4; o; o >>= 1) {
                s  += __shfl_xor_sync(0xffffffffu, s,  o);
                dd += __shfl_xor_sync(0xffffffffu, dd, o);
            }
            int grow = m0 + r;
            if ((lane & 7) == 0 && grow < M) {
                g_as[grow * 4 + h] = s;
                g_ad[grow * 4 + h] = dd;
            }
        }
    } else if (EPI == 2) {  // fused decoder tail
        __syncthreads();
        float4 wa = ((const float4*)axA)[2 * lane];
        float4 wb = ((const float4*)axA)[2 * lane + 1];
        float4 bb = *(const float4*)axB;
#pragma unroll 4
        for (int r = warp * 16; r < warp * 16 + 16; r++) {
            float u0 = scratch[r * 64 + 2 * lane];
            float u1 = scratch[r * 64 + 2 * lane + 1];
            float4 o;
            o.x = u0 * wa.x + u1 * wb.x;
            o.y = u0 * wa.y + u1 * wb.y;
            o.z = u0 * wa.z + u1 * wb.z;
            o.w = u0 * wa.w + u1 * wb.w;
#pragma unroll
            for (int of = 16; of; of >>= 1) {
                o.x += __shfl_xor_sync(0xffffffffu, o.x, of);
                o.y += __shfl_xor_sync(0xffffffffu, o.y, of);
                o.z += __shfl_xor_sync(0xffffffffu, o.z, of);
                o.w += __shfl_xor_sync(0xffffffffu, o.w, of);
            }
            int grow = m0 + r;
            if (lane == 0 && grow < M) {
                ((float4*)axO)[grow] = make_float4(o.x + bb.x, o.y + bb.y,
                                                   o.z + bb.z, o.w + bb.w);
            }
        }
    }
}

// ---------------- double fold: alpha1 directly from g_mid -----------------
__global__ void k_fold1b(const float* __restrict__ w, const float* __restrict__ as_,
                         const float* __restrict__ ad_, const float* __restrict__ w2,
                         const float* __restrict__ b2) {
    __shared__ float sw[64][4], sd[64][4];
    int t = threadIdx.x;          // t = k*4 + h
    int k = t >> 2, h = t & 3;
    float s = 0.f, d = 0.f;
#pragma unroll
    for (int c = 0; c < 64; c++) {
        float v = w[k * 256 + h * 64 + c];
        s += v * as_[h * 64 + c];
        d += v * ad_[h * 64 + c];
    }
    sw[k][h] = s;
    sd[k][h] = d;
    __syncthreads();
    float s2 = 0.f, d2 = 0.f;
#pragma unroll
    for (int o = 0; o < 64; o++) {
        float v = w2[k * 64 + o];
        s2 += v * sw[o][h];
        d2 += v * sd[o][h];
    }
    g_was[t] = s2;
    g_wad[t] = d2;
    if (t < 8) {
        int hh = t & 3;
        float acc = 0.f;
#pragma unroll
        for (int o = 0; o < 64; o++)
            acc += b2[o] * (t >= 4 ? sd[o][hh] : sw[o][hh]);
        g_aoff[t] = acc;
    }
}

// ---------------- alpha for layer 1: from g_mid via double-folded weights -
__global__ void k_alpha1(const float* __restrict__ midf) {
    int warp = (blockIdx.x * blockDim.x + threadIdx.x) >> 5;
    int lane = threadIdx.x & 31;
    if (warp >= NN) return;
    float v1 = midf[(size_t)warp * 64 + lane];
    float v2 = midf[(size_t)warp * 64 + lane + 32];
    float4 wsA = ((const float4*)g_was)[lane];
    float4 wsB = ((const float4*)g_was)[lane + 32];
    float4 wdA = ((const float4*)g_wad)[lane];
    float4 wdB = ((const float4*)g_wad)[lane + 32];
    float4 ps, pd;
    ps.x = v1 * wsA.x + v2 * wsB.x; ps.y = v1 * wsA.y + v2 * wsB.y;
    ps.z = v1 * wsA.z + v2 * wsB.z; ps.w = v1 * wsA.w + v2 * wsB.w;
    pd.x = v1 * wdA.x + v2 * wdB.x; pd.y = v1 * wdA.y + v2 * wdB.y;
    pd.z = v1 * wdA.z + v2 * wdB.z; pd.w = v1 * wdA.w + v2 * wdB.w;
#pragma unroll
    for (int o = 16; o; o >>= 1) {
        ps.x += __shfl_xor_sync(0xffffffffu, ps.x, o);
        ps.y += __shfl_xor_sync(0xffffffffu, ps.y, o);
        ps.z += __shfl_xor_sync(0xffffffffu, ps.z, o);
        ps.w += __shfl_xor_sync(0xffffffffu, ps.w, o);
        pd.x += __shfl_xor_sync(0xffffffffu, pd.x, o);
        pd.y += __shfl_xor_sync(0xffffffffu, pd.y, o);
        pd.z += __shfl_xor_sync(0xffffffffu, pd.z, o);
        pd.w += __shfl_xor_sync(0xffffffffu, pd.w, o);
    }
    if (lane == 0) {
        float4 os = ((const float4*)g_aoff)[0];
        float4 od = ((const float4*)g_aoff)[1];
        ps.x += os.x; ps.y += os.y; ps.z += os.z; ps.w += os.w;
        pd.x += od.x; pd.y += od.y; pd.z += od.z; pd.w += od.w;
        ((float4*)g_as)[warp] = ps;
        ((float4*)g_ad)[warp] = pd;
    }
}

__device__ __forceinline__ float lrelu(float e) { return e > 0.f ? e : NEG * e; }

#define RED2(v) do { \
    v.x += __shfl_xor_sync(0xffffffffu, v.x, 8);  \
    v.y += __shfl_xor_sync(0xffffffffu, v.y, 8);  \
    v.z += __shfl_xor_sync(0xffffffffu, v.z, 8);  \
    v.w += __shfl_xor_sync(0xffffffffu, v.w, 8);  \
    v.x += __shfl_xor_sync(0xffffffffu, v.x, 16); \
    v.y += __shfl_xor_sync(0xffffffffu, v.y, 16); \
    v.z += __shfl_xor_sync(0xffffffffu, v.z, 16); \
    v.w += __shfl_xor_sync(0xffffffffu, v.w, 16); \
} while (0)

// ---------------- layer-1 aggregate, quarter-warp edge-split --------------
// Quarter q (8 lanes) takes edges j = q, q+4, ...; lane covers 8 cols
// (sub*8 .. sub*8+7, two float4 loads). Combine quarters via shfl 8,16;
// quarter q writes head q's 64 columns.
__global__ void k_agg1(const float* __restrict__ h0f, float* __restrict__ aggout) {
    __shared__ float4 sh_w[8][32];
    __shared__ int    sh_s[8][32];
    int warp = (blockIdx.x * blockDim.x + threadIdx.x) >> 5;
    int lane = threadIdx.x & 31;
    if (warp >= NN) return;
    int wip = threadIdx.x >> 5;
    int q = lane >> 3, sub = lane & 7;
    int d = warp;
    int r0 = g_off[d], deg = g_off[d + 1] - r0;
    float4 adv = ((const float4*)g_ad)[d];

    float4 h0a = make_float4(0.f,0.f,0.f,0.f), h0b = h0a;
    float4 h1a = h0a, h1b = h0a, h2a = h0a, h2b = h0a, h3a = h0a, h3b = h0a;
    float s0 = 0.f, s1 = 0.f, s2 = 0.f, s3 = 0.f;

    for (int base = 0; base < deg; base += 32) {
        int n = deg - base; if (n > 32) n = 32;
        float4 w = make_float4(0.f, 0.f, 0.f, 0.f); int s = 0;
        if (lane < n) {
            s = g_srcs[r0 + base + lane];
            float4 a = ((const float4*)g_as)[s];
            w.x = __expf(lrelu(a.x + adv.x));
            w.y = __expf(lrelu(a.y + adv.y));
            w.z = __expf(lrelu(a.z + adv.z));
            w.w = __expf(lrelu(a.w + adv.w));
        }
        s0 += w.x; s1 += w.y; s2 += w.z; s3 += w.w;
        sh_w[wip][lane] = w;
        sh_s[wip][lane] = s;
        __syncwarp();
#pragma unroll 2
        for (int j = q; j < n; j += 4) {
            float4 wv = sh_w[wip][j];
            int sj = sh_s[wip][j];
            const float* hp = h0f + (size_t)sj * 64 + sub * 8;
            float4 va = *(const float4*)(hp);
            float4 vb = *(const float4*)(hp + 4);
            h0a.x += va.x*wv.x; h0a.y += va.y*wv.x; h0a.z += va.z*wv.x; h0a.w += va.w*wv.x;
            h0b.x += vb.x*wv.x; h0b.y += vb.y*wv.x; h0b.z += vb.z*wv.x; h0b.w += vb.w*wv.x;
            h1a.x += va.x*wv.y; h1a.y += va.y*wv.y; h1a.z += va.z*wv.y; h1a.w += va.w*wv.y;
            h1b.x += vb.x*wv.y; h1b.y += vb.y*wv.y; h1b.z += vb.z*wv.y; h1b.w += vb.w*wv.y;
            h2a.x += va.x*wv.z; h2a.y += va.y*wv.z; h2a.z += va.z*wv.z; h2a.w += va.w*wv.z;
            h2b.x += vb.x*wv.z; h2b.y += vb.y*wv.z; h2b.z += vb.z*wv.z; h2b.w += vb.w*wv.z;
            h3a.x += va.x*wv.w; h3a.y += va.y*wv.w; h3a.z += va.z*wv.w; h3a.w += va.w*wv.w;
            h3b.x += vb.x*wv.w; h3b.y += vb.y*wv.w; h3b.z += vb.z*wv.w; h3b.w += vb.w*wv.w;
        }
        __syncwarp();
    }
    RED2(h0a); RED2(h0b); RED2(h1a); RED2(h1b);
    RED2(h2a); RED2(h2b); RED2(h3a); RED2(h3b);
#pragma unroll
    for (int o = 16; o; o >>= 1) {
        s0 += __shfl_xor_sync(0xffffffffu, s0, o);
        s1 += __shfl_xor_sync(0xffffffffu, s1, o);
        s2 += __shfl_xor_sync(0xffffffffu, s2, o);
        s3 += __shfl_xor_sync(0xffffffffu, s3, o);
    }
    float iq = q == 0 ? 1.f / (s0 + EPSV) : q == 1 ? 1.f / (s1 + EPSV)
             : q == 2 ? 1.f / (s2 + EPSV) : 1.f / (s3 + EPSV);
    float4 oa = q == 0 ? h0a : q == 1 ? h1a : q == 2 ? h2a : h3a;
    float4 ob = q == 0 ? h0b : q == 1 ? h1b : q == 2 ? h2b : h3b;
    float* op = aggout + (size_t)d * 256 + q * 64 + sub * 8;
    *(float4*)(op)     = make_float4(oa.x*iq, oa.y*iq, oa.z*iq, oa.w*iq);
    *(float4*)(op + 4) = make_float4(ob.x*iq, ob.y*iq, ob.z*iq, ob.w*iq);
}

// ---------------- layer-2 aggregate, quarter-warp edge-split --------------
__global__ void k_agg2(const float* __restrict__ hfeat, const float* __restrict__ bias,
                       float* __restrict__ out) {
    __shared__ float4 sh_w[8][32];
    __shared__ int    sh_s[8][32];
    int warp = (blockIdx.x * blockDim.x + threadIdx.x) >> 5;
    int lane = threadIdx.x & 31;
    if (warp >= NN) return;
    int wip = threadIdx.x >> 5;
    int q = lane >> 3, sub = lane & 7;
    int headq = sub >> 1;   // 8 cols sub*8..sub*8+7 lie inside head sub>>1
    int d = warp;
    int r0 = g_off[d], deg = g_off[d + 1] - r0;
    float4 adv = ((const float4*)g_ad)[d];

    float4 aa = make_float4(0.f, 0.f, 0.f, 0.f), ab = aa;
    float s0 = 0.f, s1 = 0.f, s2 = 0.f, s3 = 0.f;
    for (int base = 0; base < deg; base += 32) {
        int n = deg - base; if (n > 32) n = 32;
        float4 w = make_float4(0.f, 0.f, 0.f, 0.f); int s = 0;
        if (lane < n) {
            s = g_srcs[r0 + base + lane];
            float4 a = ((const float4*)g_as)[s];
            w.x = __expf(lrelu(a.x + adv.x));
            w.y = __expf(lrelu(a.y + adv.y));
            w.z = __expf(lrelu(a.z + adv.z));
            w.w = __expf(lrelu(a.w + adv.w));
        }
        s0 += w.x; s1 += w.y; s2 += w.z; s3 += w.w;
        sh_w[wip][lane] = w;
        sh_s[wip][lane] = s;
        __syncwarp();
#pragma unroll 2
        for (int j = q; j < n; j += 4) {
            float4 wv = sh_w[wip][j];
            int sj = sh_s[wip][j];
            float wm = headq == 0 ? wv.x : headq == 1 ? wv.y : headq == 2 ? wv.z : wv.w;
            const float* hp = hfeat + (size_t)sj * 64 + sub * 8;
            float4 va = *(const float4*)(hp);
            float4 vb = *(const float4*)(hp + 4);
            aa.x += va.x * wm; aa.y += va.y * wm; aa.z += va.z * wm; aa.w += va.w * wm;
            ab.x += vb.x * wm; ab.y += vb.y * wm; ab.z += vb.z * wm; ab.w += vb.w * wm;
        }
        __syncwarp();
    }
    RED2(aa); RED2(ab);
#pragma unroll
    for (int o = 16; o; o >>= 1) {
        s0 += __shfl_xor_sync(0xffffffffu, s0, o);
        s1 += __shfl_xor_sync(0xffffffffu, s1, o);
        s2 += __shfl_xor_sync(0xffffffffu, s2, o);
        s3 += __shfl_xor_sync(0xffffffffu, s3, o);
    }
    if (q == 0) {
        float im = headq == 0 ? 1.f / (s0 + EPSV) : headq == 1 ? 1.f / (s1 + EPSV)
                 : headq == 2 ? 1.f / (s2 + EPSV) : 1.f / (s3 + EPSV);
        const float* bp = bias + sub * 8;
        float4 b0 = *(const float4*)(bp);
        float4 b1 = *(const float4*)(bp + 4);
        float* op = out + (size_t)d * 64 + sub * 8;
        *(float4*)(op)     = make_float4(aa.x*im + b0.x, aa.y*im + b0.y,
                                         aa.z*im + b0.z, aa.w*im + b0.w);
        *(float4*)(op + 4) = make_float4(ab.x*im + b1.x, ab.y*im + b1.y,
                                         ab.z*im + b1.z, ab.w*im + b1.w);
    }
}

// ---------------- launch ----------------
extern "C" void kernel_launch(void* const* d_in, const int* in_sizes, int n_in,
                              void* d_out, int out_size) {
    const float* x      = (const float*)d_in[0];
    const int*   ei     = (const int*)  d_in[1];
    const float* enc_w1 = (const float*)d_in[2];
    const float* enc_b1 = (const float*)d_in[3];
    const float* enc_w2 = (const float*)d_in[4];
    const float* enc_b2 = (const float*)d_in[5];
    const float* g1_w   = (const float*)d_in[6];
    const float* g1_as  = (const float*)d_in[7];
    const float* g1_ad  = (const float*)d_in[8];
    const float* g1_b   = (const float*)d_in[9];
    const float* g2_w   = (const float*)d_in[10];
    const float* g2_as  = (const float*)d_in[11];
    const float* g2_ad  = (const float*)d_in[12];
    const float* g2_b   = (const float*)d_in[13];
    const float* dec_w1 = (const float*)d_in[14];
    const float* dec_b1 = (const float*)d_in[15];
    const float* dec_w2 = (const float*)d_in[16];
    const float* dec_b2 = (const float*)d_in[17];
    float* out = (float*)d_out;

    float *mid, *h0, *agg, *o1, *h2, *o2;
    cudaGetSymbolAddress((void**)&mid, g_mid);
    cudaGetSymbolAddress((void**)&h0,  g_h0);
    cudaGetSymbolAddress((void**)&agg, g_agg);
    cudaGetSymbolAddress((void**)&o1,  g_o1);
    cudaGetSymbolAddress((void**)&h2,  g_h2);
    cudaGetSymbolAddress((void**)&o2,  g_o2);
    void* degp;
    cudaGetSymbolAddress(&degp, g_deg);

    static cudaStream_t s1 = 0, s2 = 0;
    static cudaEvent_t evRoot = 0, evCSR = 0, evMid = 0, evAlpha = 0;
    static int inited = 0;
    if (!inited) {
        cudaStreamCreateWithFlags(&s1, cudaStreamNonBlocking);
        cudaStreamCreateWithFlags(&s2, cudaStreamNonBlocking);
        cudaEventCreateWithFlags(&evRoot,  cudaEventDisableTiming);
        cudaEventCreateWithFlags(&evCSR,   cudaEventDisableTiming);
        cudaEventCreateWithFlags(&evMid,   cudaEventDisableTiming);
        cudaEventCreateWithFlags(&evAlpha, cudaEventDisableTiming);
        inited = 1;
    }

    const int WPB = 6250;      // 50000 warps / 8 warps-per-block
    const int GY  = (NN + 127) / 128;

    // ---- fork ----
    cudaEventRecord(evRoot, 0);
    cudaStreamWaitEvent(s1, evRoot, 0);
    cudaStreamWaitEvent(s2, evRoot, 0);

    // branch s1: CSR build
    cudaMemsetAsync(degp, 0, NN * sizeof(int), s1);
    k_count<<<(ETOT + 255) / 256, 256, 0, s1>>>(ei);
    k_bsum<<<NB1, 1024, 0, s1>>>();
    k_swrite<<<NB1, 1024, 0, s1>>>();
    k_scatter<<<(ETOT + 255) / 256, 256, 0, s1>>>(ei);
    cudaEventRecord(evCSR, s1);

    // branch s2: double-fold, then alpha1 from mid (parallel with enc2 GEMM)
    k_fold1b<<<1, 256, 0, s2>>>(g1_w, g1_as, g1_ad, enc_w2, enc_b2);

    // main: encoder
    k_enc1<<<(NN * 64 + 255) / 256, 256>>>(x, enc_w1, enc_b1);
    cudaEventRecord(evMid, 0);
    cudaStreamWaitEvent(s2, evMid, 0);
    k_alpha1<<<WPB, 256, 0, s2>>>(mid);
    cudaEventRecord(evAlpha, s2);

    k_mma_gemm<0, 0><<<dim3(1, GY), 256>>>(mid, enc_w2, enc_b2, h0,
                                           NN, 64, 64, 64, 64, 64, 0,
                                           nullptr, nullptr, nullptr);

    // ---- join: aggregation needs CSR + alpha1 + h0 ----
    cudaStreamWaitEvent(0, evCSR, 0);
    cudaStreamWaitEvent(0, evAlpha, 0);
    k_agg1<<<WPB, 256>>>(h0, agg);
    k_mma_gemm<2, 0><<<dim3(1, GY, 4), 256>>>(agg, g1_w, g1_b, o1,
                                              NN, 64, 64, 256, 256, 256, 64,
                                              nullptr, nullptr, nullptr);

    // GAT layer 2 weight GEMM with fused alpha2 epilogue
    k_mma_gemm<0, 1><<<dim3(1, GY), 256>>>(o1, g2_w, nullptr, h2,
                                           NN, 256, 64, 256, 64, 64, 0,
                                           g2_as, g2_ad, nullptr);
    k_agg2<<<WPB, 256>>>(h2, g2_b, o2);

    // decoder: one GEMM with fused final-layer epilogue (writes out directly)
    k_mma_gemm<1, 2><<<dim3(1, GY), 256>>>(o2, dec_w1, dec_b1, nullptr,
                                           NN, 64, 64, 64, 64, 64, 0,
                                           dec_w2, dec_b2, out);
}

// round 13
// speedup vs baseline: 1.4188x; 1.1513x over previous
#include <cuda_runtime.h>
#include <math.h>
#include <stdint.h>

#define NN 50000
#define NE 800000
#define ETOT (NE + NN)
#define NEG 0.2f
#define EPSV 1e-16f
#define NB1 49   // ceil(NN/1024)

// ---------------- scratch (device globals; no allocation allowed) ----------
__device__ __align__(16) float g_mid[NN * 64];
__device__ __align__(16) float g_h0 [NN * 64];
__device__ __align__(16) float g_agg[NN * 256];
__device__ __align__(16) float g_o1 [NN * 256];
__device__ __align__(16) float g_h2 [NN * 64];
__device__ __align__(16) float g_o2 [NN * 64];
__device__ __align__(16) float g_as [NN * 4];
__device__ __align__(16) float g_ad [NN * 4];
__device__ __align__(16) float g_was[256];
__device__ __align__(16) float g_wad[256];
__device__ __align__(16) float g_aoff[8];
__device__ int g_deg[NN];
__device__ int g_off[NN + 1];
__device__ int g_srcs[ETOT];
__device__ int g_epos[ETOT];

// ---------------- CSR build ----------------
__global__ void k_count(const int* __restrict__ ei) {
    int i = blockIdx.x * blockDim.x + threadIdx.x;
    if (i >= ETOT) return;
    int d = (i < NE) ? ei[NE + i] : (i - NE);
    g_epos[i] = atomicAdd(&g_deg[d], 1);
}

// scan kernel: each block re-sums all preceding degrees for its base
// (redundant but cheap: <=49 coalesced loads/thread, L2-resident),
// then does its own 1024-wide inclusive scan. Replaces bsum+swrite.
__global__ void k_swrite() {
    __shared__ int sh[1024];
    int t = threadIdx.x;
    int b = blockIdx.x;
    int part = 0;
    for (int i = t; i < b * 1024; i += 1024) part += g_deg[i];
    sh[t] = part;
    __syncthreads();
#pragma unroll
    for (int o = 512; o > 0; o >>= 1) {
        if (t < o) sh[t] += sh[t + o];
        __syncthreads();
    }
    int base = sh[0];
    __syncthreads();
    int i = b * 1024 + t;
    int v = (i < NN) ? g_deg[i] : 0;
    sh[t] = v;
    __syncthreads();
#pragma unroll
    for (int o = 1; o < 1024; o <<= 1) {
        int x = (t >= o) ? sh[t - o] : 0;
        __syncthreads();
        sh[t] += x;
        __syncthreads();
    }
    int incl = sh[t];
    if (i < NN) {
        g_off[i] = base + incl - v;
        if (i == NN - 1) g_off[NN] = base + incl;
    }
}

__global__ void k_scatter(const int* __restrict__ ei) {
    int i = blockIdx.x * blockDim.x + threadIdx.x;
    if (i >= ETOT) return;
    int s, d;
    if (i < NE) { s = ei[i]; d = ei[NE + i]; }
    else        { s = i - NE; d = i - NE; }
    g_srcs[g_off[d] + g_epos[i]] = s;
}

// ---------------- encoder first layer (K=7) ----------------
__global__ void k_enc1(const float* __restrict__ x, const float* __restrict__ w1,
                       const float* __restrict__ b1) {
    int idx = blockIdx.x * blockDim.x + threadIdx.x;
    if (idx >= NN * 64) return;
    int n = idx >> 6, c = idx & 63;
    float s = b1[c];
#pragma unroll
    for (int k = 0; k < 7; k++) s += x[n * 7 + k] * w1[k * 64 + c];
    g_mid[idx] = fmaxf(s, 0.f);
}

// ---------------- tf32 tensor-core GEMM (2xTF32: exact A, tf32 B) ---------
__device__ __forceinline__ float tf32_rn(float x) {
    uint32_t u;
    asm("cvt.rna.tf32.f32 %0, %1;" : "=r"(u) : "f"(x));
    return __uint_as_float(u);
}

__device__ __forceinline__ void mma_tf32(float4& d, const uint32_t a[4], const uint32_t b[2]) {
    asm volatile(
        "mma.sync.aligned.m16n8k8.row.col.f32.tf32.tf32.f32 "
        "{%0,%1,%2,%3},{%4,%5,%6,%7},{%8,%9},{%0,%1,%2,%3};\n"
        : "+f"(d.x), "+f"(d.y), "+f"(d.z), "+f"(d.w)
        : "r"(a[0]), "r"(a[1]), "r"(a[2]), "r"(a[3]), "r"(b[0]), "r"(b[1]));
}

// ACT: 0 none, 1 relu, 2 elu
// EPI: 0 normal store
//      1 store C AND compute layer-2 alphas from the 128x64 tile (axA=as, axB=ad)
//      2 decoder: relu tile, NO C store; out[r,0:4] = tile @ axA(64x4) + axB(4); axO=out
template <int ACT, int EPI>
__global__ void k_mma_gemm(const float* __restrict__ A, const float* __restrict__ B,
                           const float* __restrict__ bias, float* __restrict__ C,
                           int M, int K, int Nc, int lda, int ldb, int ldc, int zoff,
                           const float* __restrict__ axA, const float* __restrict__ axB,
                           float* __restrict__ axO) {
    __shared__ __align__(16) float smbuf[8192];
    float (*Ah)[136] = (float(*)[136])(smbuf);
    float (*Al)[136] = (float(*)[136])(smbuf + 16 * 136);
    float (*Bh)[72]  = (float(*)[72]) (smbuf + 2 * 16 * 136);
    float* scratch   = smbuf;

    int zo = blockIdx.z * zoff;
    A += zo; B += zo;
    if (C) C += zo;
    if (bias) bias += zo;

    int tid  = threadIdx.x;
    int warp = tid >> 5, lane = tid & 31;
    int wm = warp >> 1, wn = warp & 1;
    int m0 = blockIdx.y * 128, n0 = blockIdx.x * 64;
    int grp = lane >> 2, tig = lane & 3;

    float4 acc[2][4];
#pragma unroll
    for (int i = 0; i < 2; i++)
#pragma unroll
        for (int j = 0; j < 4; j++) acc[i][j] = make_float4(0.f, 0.f, 0.f, 0.f);

    for (int k0 = 0; k0 < K; k0 += 16) {
#pragma unroll
        for (int r = 0; r < 2; r++) {
            int idx = tid + 256 * r;
            int m = idx >> 2, kq = idx & 3;
            int row = m0 + m;
            float4 v = make_float4(0.f, 0.f, 0.f, 0.f);
            if (row < M) v = *(const float4*)(A + (size_t)row * lda + k0 + 4 * kq);
            float h;
            h = tf32_rn(v.x); Ah[4*kq+0][m] = h; Al[4*kq+0][m] = tf32_rn(v.x - h);
            h = tf32_rn(v.y); Ah[4*kq+1][m] = h; Al[4*kq+1][m] = tf32_rn(v.y - h);
            h = tf32_rn(v.z); Ah[4*kq+2][m] = h; Al[4*kq+2][m] = tf32_rn(v.z - h);
            h = tf32_rn(v.w); Ah[4*kq+3][m] = h; Al[4*kq+3][m] = tf32_rn(v.w - h);
        }
        {
            int kk = tid >> 4, nq = tid & 15;
            float4 v = *(const float4*)(B + (size_t)(k0 + kk) * ldb + n0 + 4 * nq);
            float4 hv;
            hv.x = tf32_rn(v.x);
            hv.y = tf32_rn(v.y);
            hv.z = tf32_rn(v.z);
            hv.w = tf32_rn(v.w);
            *(float4*)&Bh[kk][4 * nq] = hv;
        }
        __syncthreads();

#pragma unroll
        for (int ks = 0; ks < 2; ks++) {
            int kb = ks * 8;
            uint32_t aH[2][4], aL[2][4];
#pragma unroll
            for (int mt = 0; mt < 2; mt++) {
                int mb = wm * 32 + mt * 16 + grp;
                aH[mt][0] = __float_as_uint(Ah[kb + tig    ][mb]);
                aH[mt][1] = __float_as_uint(Ah[kb + tig    ][mb + 8]);
                aH[mt][2] = __float_as_uint(Ah[kb + tig + 4][mb]);
                aH[mt][3] = __float_as_uint(Ah[kb + tig + 4][mb + 8]);
                aL[mt][0] = __float_as_uint(Al[kb + tig    ][mb]);
                aL[mt][1] = __float_as_uint(Al[kb + tig    ][mb + 8]);
                aL[mt][2] = __float_as_uint(Al[kb + tig + 4][mb]);
                aL[mt][3] = __float_as_uint(Al[kb + tig + 4][mb + 8]);
            }
#pragma unroll
            for (int nt = 0; nt < 4; nt++) {
                int nb = wn * 32 + nt * 8 + grp;
                uint32_t bH[2];
                bH[0] = __float_as_uint(Bh[kb + tig    ][nb]);
                bH[1] = __float_as_uint(Bh[kb + tig + 4][nb]);
#pragma unroll
                for (int mt = 0; mt < 2; mt++) {
                    mma_tf32(acc[mt][nt], aH[mt], bH);
                    mma_tf32(acc[mt][nt], aL[mt], bH);
                }
            }
        }
        __syncthreads();
    }

#pragma unroll
    for (int mt = 0; mt < 2; mt++) {
#pragma unroll
        for (int nt = 0; nt < 4; nt++) {
            int lc  = wn * 32 + nt * 8 + 2 * tig;
            int col = n0 + lc;
            float b0 = bias ? bias[col] : 0.f;
            float b1 = bias ? bias[col + 1] : 0.f;
            int lr  = wm * 32 + mt * 16 + grp;
            int rt_ = m0 + lr;
            float2 v0 = make_float2(acc[mt][nt].x + b0, acc[mt][nt].y + b1);
            float2 v1 = make_float2(acc[mt][nt].z + b0, acc[mt][nt].w + b1);
            if (ACT == 1) {
                v0.x = fmaxf(v0.x, 0.f); v0.y = fmaxf(v0.y, 0.f);
                v1.x = fmaxf(v1.x, 0.f); v1.y = fmaxf(v1.y, 0.f);
            } else if (ACT == 2) {
                v0.x = v0.x > 0.f ? v0.x : expm1f(v0.x);
                v0.y = v0.y > 0.f ? v0.y : expm1f(v0.y);
                v1.x = v1.x > 0.f ? v1.x : expm1f(v1.x);
                v1.y = v1.y > 0.f ? v1.y : expm1f(v1.y);
            }
            if (EPI != 2) {
                if (rt_ < M)     *(float2*)(C + (size_t)rt_ * ldc + col)       = v0;
                if (rt_ + 8 < M) *(float2*)(C + (size_t)(rt_ + 8) * ldc + col) = v1;
            }
            if (EPI != 0) {
                scratch[lr * 64 + lc]           = v0.x;
                scratch[lr * 64 + lc + 1]       = v0.y;
                scratch[(lr + 8) * 64 + lc]     = v1.x;
                scratch[(lr + 8) * 64 + lc + 1] = v1.y;
            }
        }
    }

    if (EPI == 1) {   // fused layer-2 alpha
        __syncthreads();
        float a0 = axA[2 * lane], a1 = axA[2 * lane + 1];
        float d0 = axB[2 * lane], d1 = axB[2 * lane + 1];
        int h = lane >> 3;
#pragma unroll 4
        for (int r = warp * 16; r < warp * 16 + 16; r++) {
            float u0 = scratch[r * 64 + 2 * lane];
            float u1 = scratch[r * 64 + 2 * lane + 1];
            float s  = u0 * a0 + u1 * a1;
            float dd = u0 * d0 + u1 * d1;
#pragma unroll
            for (int o = 4; o; o >>= 1) {
                s  += __shfl_xor_sync(0xffffffffu, s,  o);
                dd += __shfl_xor_sync(0xffffffffu, dd, o);
            }
            int grow = m0 + r;
            if ((lane & 7) == 0 && grow < M) {
                g_as[grow * 4 + h] = s;
                g_ad[grow * 4 + h] = dd;
            }
        }
    } else if (EPI == 2) {  // fused decoder tail
        __syncthreads();
        float4 wa = ((const float4*)axA)[2 * lane];
        float4 wb = ((const float4*)axA)[2 * lane + 1];
        float4 bb = *(const float4*)axB;
#pragma unroll 4
        for (int r = warp * 16; r < warp * 16 + 16; r++) {
            float u0 = scratch[r * 64 + 2 * lane];
            float u1 = scratch[r * 64 + 2 * lane + 1];
            float4 o;
            o.x = u0 * wa.x + u1 * wb.x;
            o.y = u0 * wa.y + u1 * wb.y;
            o.z = u0 * wa.z + u1 * wb.z;
            o.w = u0 * wa.w + u1 * wb.w;
#pragma unroll
            for (int of = 16; of; of >>= 1) {
                o.x += __shfl_xor_sync(0xffffffffu, o.x, of);
                o.y += __shfl_xor_sync(0xffffffffu, o.y, of);
                o.z += __shfl_xor_sync(0xffffffffu, o.z, of);
                o.w += __shfl_xor_sync(0xffffffffu, o.w, of);
            }
            int grow = m0 + r;
            if (lane == 0 && grow < M) {
                ((float4*)axO)[grow] = make_float4(o.x + bb.x, o.y + bb.y,
                                                   o.z + bb.z, o.w + bb.w);
            }
        }
    }
}

// ---------------- double fold: alpha1 directly from g_mid -----------------
__global__ void k_fold1b(const float* __restrict__ w, const float* __restrict__ as_,
                         const float* __restrict__ ad_, const float* __restrict__ w2,
                         const float* __restrict__ b2) {
    __shared__ float sw[64][4], sd[64][4];
    int t = threadIdx.x;          // t = k*4 + h
    int k = t >> 2, h = t & 3;
    float s = 0.f, d = 0.f;
#pragma unroll
    for (int c = 0; c < 64; c++) {
        float v = w[k * 256 + h * 64 + c];
        s += v * as_[h * 64 + c];
        d += v * ad_[h * 64 + c];
    }
    sw[k][h] = s;
    sd[k][h] = d;
    __syncthreads();
    float s2 = 0.f, d2 = 0.f;
#pragma unroll
    for (int o = 0; o < 64; o++) {
        float v = w2[k * 64 + o];
        s2 += v * sw[o][h];
        d2 += v * sd[o][h];
    }
    g_was[t] = s2;
    g_wad[t] = d2;
    if (t < 8) {
        int hh = t & 3;
        float acc = 0.f;
#pragma unroll
        for (int o = 0; o < 64; o++)
            acc += b2[o] * (t >= 4 ? sd[o][hh] : sw[o][hh]);
        g_aoff[t] = acc;
    }
}

// ---------------- alpha for layer 1: from g_mid via double-folded weights -
__global__ void k_alpha1(const float* __restrict__ midf) {
    int warp = (blockIdx.x * blockDim.x + threadIdx.x) >> 5;
    int lane = threadIdx.x & 31;
    if (warp >= NN) return;
    float v1 = midf[(size_t)warp * 64 + lane];
    float v2 = midf[(size_t)warp * 64 + lane + 32];
    float4 wsA = ((const float4*)g_was)[lane];
    float4 wsB = ((const float4*)g_was)[lane + 32];
    float4 wdA = ((const float4*)g_wad)[lane];
    float4 wdB = ((const float4*)g_wad)[lane + 32];
    float4 ps, pd;
    ps.x = v1 * wsA.x + v2 * wsB.x; ps.y = v1 * wsA.y + v2 * wsB.y;
    ps.z = v1 * wsA.z + v2 * wsB.z; ps.w = v1 * wsA.w + v2 * wsB.w;
    pd.x = v1 * wdA.x + v2 * wdB.x; pd.y = v1 * wdA.y + v2 * wdB.y;
    pd.z = v1 * wdA.z + v2 * wdB.z; pd.w = v1 * wdA.w + v2 * wdB.w;
#pragma unroll
    for (int o = 16; o; o >>= 1) {
        ps.x += __shfl_xor_sync(0xffffffffu, ps.x, o);
        ps.y += __shfl_xor_sync(0xffffffffu, ps.y, o);
        ps.z += __shfl_xor_sync(0xffffffffu, ps.z, o);
        ps.w += __shfl_xor_sync(0xffffffffu, ps.w, o);
        pd.x += __shfl_xor_sync(0xffffffffu, pd.x, o);
        pd.y += __shfl_xor_sync(0xffffffffu, pd.y, o);
        pd.z += __shfl_xor_sync(0xffffffffu, pd.z, o);
        pd.w += __shfl_xor_sync(0xffffffffu, pd.w, o);
    }
    if (lane == 0) {
        float4 os = ((const float4*)g_aoff)[0];
        float4 od = ((const float4*)g_aoff)[1];
        ps.x += os.x; ps.y += os.y; ps.z += os.z; ps.w += os.w;
        pd.x += od.x; pd.y += od.y; pd.z += od.z; pd.w += od.w;
        ((float4*)g_as)[warp] = ps;
        ((float4*)g_ad)[warp] = pd;
    }
}

__device__ __forceinline__ float lrelu(float e) { return e > 0.f ? e : NEG * e; }

// ---------------- layer-1 aggregate, half-warp edge-split -----------------
__global__ void k_agg1(const float* __restrict__ h0f, float* __restrict__ aggout) {
    __shared__ float4 sh_w[8][32];
    __shared__ int    sh_s[8][32];
    int warp = (blockIdx.x * blockDim.x + threadIdx.x) >> 5;
    int lane = threadIdx.x & 31;
    if (warp >= NN) return;
    int wip = threadIdx.x >> 5;
    int half = lane >> 4, sub = lane & 15;
    int d = warp;
    int r0 = g_off[d], deg = g_off[d + 1] - r0;
    float4 adv = ((const float4*)g_ad)[d];

    float4 A0 = make_float4(0.f,0.f,0.f,0.f), A1 = A0, A2 = A0, A3 = A0;
    float s0 = 0.f, s1 = 0.f, s2 = 0.f, s3 = 0.f;

    for (int base = 0; base < deg; base += 32) {
        int n = deg - base; if (n > 32) n = 32;
        float4 w = make_float4(0.f, 0.f, 0.f, 0.f); int s = 0;
        if (lane < n) {
            s = g_srcs[r0 + base + lane];
            float4 a = ((const float4*)g_as)[s];
            w.x = __expf(lrelu(a.x + adv.x));
            w.y = __expf(lrelu(a.y + adv.y));
            w.z = __expf(lrelu(a.z + adv.z));
            w.w = __expf(lrelu(a.w + adv.w));
        }
        s0 += w.x; s1 += w.y; s2 += w.z; s3 += w.w;
        sh_w[wip][lane] = w;
        sh_s[wip][lane] = s;
        __syncwarp();
#pragma unroll 4
        for (int j = half; j < n; j += 2) {
            float4 wv = sh_w[wip][j];
            int sj = sh_s[wip][j];
            float4 v = *(const float4*)(h0f + (size_t)sj * 64 + sub * 4);
            A0.x += v.x*wv.x; A0.y += v.y*wv.x; A0.z += v.z*wv.x; A0.w += v.w*wv.x;
            A1.x += v.x*wv.y; A1.y += v.y*wv.y; A1.z += v.z*wv.y; A1.w += v.w*wv.y;
            A2.x += v.x*wv.z; A2.y += v.y*wv.z; A2.z += v.z*wv.z; A2.w += v.w*wv.z;
            A3.x += v.x*wv.w; A3.y += v.y*wv.w; A3.z += v.z*wv.w; A3.w += v.w*wv.w;
        }
        __syncwarp();
    }
    A0.x += __shfl_xor_sync(0xffffffffu, A0.x, 16);
    A0.y += __shfl_xor_sync(0xffffffffu, A0.y, 16);
    A0.z += __shfl_xor_sync(0xffffffffu, A0.z, 16);
    A0.w += __shfl_xor_sync(0xffffffffu, A0.w, 16);
    A1.x += __shfl_xor_sync(0xffffffffu, A1.x, 16);
    A1.y += __shfl_xor_sync(0xffffffffu, A1.y, 16);
    A1.z += __shfl_xor_sync(0xffffffffu, A1.z, 16);
    A1.w += __shfl_xor_sync(0xffffffffu, A1.w, 16);
    A2.x += __shfl_xor_sync(0xffffffffu, A2.x, 16);
    A2.y += __shfl_xor_sync(0xffffffffu, A2.y, 16);
    A2.z += __shfl_xor_sync(0xffffffffu, A2.z, 16);
    A2.w += __shfl_xor_sync(0xffffffffu, A2.w, 16);
    A3.x += __shfl_xor_sync(0xffffffffu, A3.x, 16);
    A3.y += __shfl_xor_sync(0xffffffffu, A3.y, 16);
    A3.z += __shfl_xor_sync(0xffffffffu, A3.z, 16);
    A3.w += __shfl_xor_sync(0xffffffffu, A3.w, 16);
#pragma unroll
    for (int o = 16; o; o >>= 1) {
        s0 += __shfl_xor_sync(0xffffffffu, s0, o);
        s1 += __shfl_xor_sync(0xffffffffu, s1, o);
        s2 += __shfl_xor_sync(0xffffffffu, s2, o);
        s3 += __shfl_xor_sync(0xffffffffu, s3, o);
    }
    float i0 = 1.f / (s0 + EPSV), i1 = 1.f / (s1 + EPSV);
    float i2 = 1.f / (s2 + EPSV), i3 = 1.f / (s3 + EPSV);
    float* ob = aggout + (size_t)d * 256 + sub * 4;
    if (half == 0) {
        *(float4*)(ob)      = make_float4(A0.x*i0, A0.y*i0, A0.z*i0, A0.w*i0);
        *(float4*)(ob + 64) = make_float4(A1.x*i1, A1.y*i1, A1.z*i1, A1.w*i1);
    } else {
        *(float4*)(ob + 128) = make_float4(A2.x*i2, A2.y*i2, A2.z*i2, A2.w*i2);
        *(float4*)(ob + 192) = make_float4(A3.x*i3, A3.y*i3, A3.z*i3, A3.w*i3);
    }
}

// ---------------- layer-2 aggregate, half-warp edge-split -----------------
__global__ void k_agg2(const float* __restrict__ hfeat, const float* __restrict__ bias,
                       float* __restrict__ out) {
    __shared__ float4 sh_w[8][32];
    __shared__ int    sh_s[8][32];
    int warp = (blockIdx.x * blockDim.x + threadIdx.x) >> 5;
    int lane = threadIdx.x & 31;
    if (warp >= NN) return;
    int wip = threadIdx.x >> 5;
    int half = lane >> 4, sub = lane & 15;
    int headq = sub >> 2;
    int d = warp;
    int r0 = g_off[d], deg = g_off[d + 1] - r0;
    float4 adv = ((const float4*)g_ad)[d];

    float4 acc = make_float4(0.f, 0.f, 0.f, 0.f);
    float s0 = 0.f, s1 = 0.f, s2 = 0.f, s3 = 0.f;
    for (int base = 0; base < deg; base += 32) {
        int n = deg - base; if (n > 32) n = 32;
        float4 w = make_float4(0.f, 0.f, 0.f, 0.f); int s = 0;
        if (lane < n) {
            s = g_srcs[r0 + base + lane];
            float4 a = ((const float4*)g_as)[s];
            w.x = __expf(lrelu(a.x + adv.x));
            w.y = __expf(lrelu(a.y + adv.y));
            w.z = __expf(lrelu(a.z + adv.z));
            w.w = __expf(lrelu(a.w + adv.w));
        }
        s0 += w.x; s1 += w.y; s2 += w.z; s3 += w.w;
        sh_w[wip][lane] = w;
        sh_s[wip][lane] = s;
        __syncwarp();
#pragma unroll 4
        for (int j = half; j < n; j += 2) {
            float4 wv = sh_w[wip][j];
            int sj = sh_s[wip][j];
            float wm = headq == 0 ? wv.x : headq == 1 ? wv.y : headq == 2 ? wv.z : wv.w;
            float4 v = *(const float4*)(hfeat + (size_t)sj * 64 + sub * 4);
            acc.x += v.x * wm; acc.y += v.y * wm;
            acc.z += v.z * wm; acc.w += v.w * wm;
        }
        __syncwarp();
    }
    acc.x += __shfl_xor_sync(0xffffffffu, acc.x, 16);
    acc.y += __shfl_xor_sync(0xffffffffu, acc.y, 16);
    acc.z += __shfl_xor_sync(0xffffffffu, acc.z, 16);
    acc.w += __shfl_xor_sync(0xffffffffu, acc.w, 16);
#pragma unroll
    for (int o = 16; o; o >>= 1) {
        s0 += __shfl_xor_sync(0xffffffffu, s0, o);
        s1 += __shfl_xor_sync(0xffffffffu, s1, o);
        s2 += __shfl_xor_sync(0xffffffffu, s2, o);
        s3 += __shfl_xor_sync(0xffffffffu, s3, o);
    }
    if (half == 0) {
        float im = headq == 0 ? 1.f / (s0 + EPSV) : headq == 1 ? 1.f / (s1 + EPSV)
                 : headq == 2 ? 1.f / (s2 + EPSV) : 1.f / (s3 + EPSV);
        float4 bv = ((const float4*)bias)[sub];
        float4 r;
        r.x = acc.x * im + bv.x;
        r.y = acc.y * im + bv.y;
        r.z = acc.z * im + bv.z;
        r.w = acc.w * im + bv.w;
        ((float4*)(out + (size_t)d * 64))[sub] = r;
    }
}

// ---------------- launch ----------------
extern "C" void kernel_launch(void* const* d_in, const int* in_sizes, int n_in,
                              void* d_out, int out_size) {
    const float* x      = (const float*)d_in[0];
    const int*   ei     = (const int*)  d_in[1];
    const float* enc_w1 = (const float*)d_in[2];
    const float* enc_b1 = (const float*)d_in[3];
    const float* enc_w2 = (const float*)d_in[4];
    const float* enc_b2 = (const float*)d_in[5];
    const float* g1_w   = (const float*)d_in[6];
    const float* g1_as  = (const float*)d_in[7];
    const float* g1_ad  = (const float*)d_in[8];
    const float* g1_b   = (const float*)d_in[9];
    const float* g2_w   = (const float*)d_in[10];
    const float* g2_as  = (const float*)d_in[11];
    const float* g2_ad  = (const float*)d_in[12];
    const float* g2_b   = (const float*)d_in[13];
    const float* dec_w1 = (const float*)d_in[14];
    const float* dec_b1 = (const float*)d_in[15];
    const float* dec_w2 = (const float*)d_in[16];
    const float* dec_b2 = (const float*)d_in[17];
    float* out = (float*)d_out;

    float *mid, *h0, *agg, *o1, *h2, *o2;
    cudaGetSymbolAddress((void**)&mid, g_mid);
    cudaGetSymbolAddress((void**)&h0,  g_h0);
    cudaGetSymbolAddress((void**)&agg, g_agg);
    cudaGetSymbolAddress((void**)&o1,  g_o1);
    cudaGetSymbolAddress((void**)&h2,  g_h2);
    cudaGetSymbolAddress((void**)&o2,  g_o2);
    void* degp;
    cudaGetSymbolAddress(&degp, g_deg);

    static cudaStream_t s1 = 0, s2 = 0;
    static cudaEvent_t evRoot = 0, evCSR = 0, evMid = 0, evAlpha = 0;
    static int inited = 0;
    if (!inited) {
        cudaStreamCreateWithFlags(&s1, cudaStreamNonBlocking);
        cudaStreamCreateWithFlags(&s2, cudaStreamNonBlocking);
        cudaEventCreateWithFlags(&evRoot,  cudaEventDisableTiming);
        cudaEventCreateWithFlags(&evCSR,   cudaEventDisableTiming);
        cudaEventCreateWithFlags(&evMid,   cudaEventDisableTiming);
        cudaEventCreateWithFlags(&evAlpha, cudaEventDisableTiming);
        inited = 1;
    }

    const int WPB = 6250;      // 50000 warps / 8 warps-per-block
    const int GY  = (NN + 127) / 128;

    // ---- fork ----
    cudaEventRecord(evRoot, 0);
    cudaStreamWaitEvent(s1, evRoot, 0);
    cudaStreamWaitEvent(s2, evRoot, 0);

    // branch s1: CSR build (3 kernels + memset)
    cudaMemsetAsync(degp, 0, NN * sizeof(int), s1);
    k_count<<<(ETOT + 255) / 256, 256, 0, s1>>>(ei);
    k_swrite<<<NB1, 1024, 0, s1>>>();
    k_scatter<<<(ETOT + 255) / 256, 256, 0, s1>>>(ei);
    cudaEventRecord(evCSR, s1);

    // branch s2: double-fold, then alpha1 from mid (parallel with enc2 GEMM)
    k_fold1b<<<1, 256, 0, s2>>>(g1_w, g1_as, g1_ad, enc_w2, enc_b2);

    // main: encoder
    k_enc1<<<(NN * 64 + 255) / 256, 256>>>(x, enc_w1, enc_b1);
    cudaEventRecord(evMid, 0);
    cudaStreamWaitEvent(s2, evMid, 0);
    k_alpha1<<<WPB, 256, 0, s2>>>(mid);
    cudaEventRecord(evAlpha, s2);

    k_mma_gemm<0, 0><<<dim3(1, GY), 256>>>(mid, enc_w2, enc_b2, h0,
                                           NN, 64, 64, 64, 64, 64, 0,
                                           nullptr, nullptr, nullptr);

    // ---- join: aggregation needs CSR + alpha1 + h0 ----
    cudaStreamWaitEvent(0, evCSR, 0);
    cudaStreamWaitEvent(0, evAlpha, 0);
    k_agg1<<<WPB, 256>>>(h0, agg);
    k_mma_gemm<2, 0><<<dim3(1, GY, 4), 256>>>(agg, g1_w, g1_b, o1,
                                              NN, 64, 64, 256, 256, 256, 64,
                                              nullptr, nullptr, nullptr);

    // GAT layer 2 weight GEMM with fused alpha2 epilogue
    k_mma_gemm<0, 1><<<dim3(1, GY), 256>>>(o1, g2_w, nullptr, h2,
                                           NN, 256, 64, 256, 64, 64, 0,
                                           g2_as, g2_ad, nullptr);
    k_agg2<<<WPB, 256>>>(h2, g2_b, o2);

    // decoder: one GEMM with fused final-layer epilogue (writes out directly)
    k_mma_gemm<1, 2><<<dim3(1, GY), 256>>>(o2, dec_w1, dec_b1, nullptr,
                                           NN, 64, 64, 64, 64, 64, 0,
                                           dec_w2, dec_b2, out);
}

// round 14
// speedup vs baseline: 1.4220x; 1.0022x over previous
#include <cuda_runtime.h>
#include <math.h>
#include <stdint.h>

#define NN 50000
#define NE 800000
#define ETOT (NE + NN)
#define NEG 0.2f
#define EPSV 1e-16f
#define NB1 49   // ceil(NN/1024)

// ---------------- scratch (device globals; no allocation allowed) ----------
__device__ __align__(16) float g_mid[NN * 64];
__device__ __align__(16) float g_h0 [NN * 64];
__device__ __align__(16) float g_agg[NN * 256];
__device__ __align__(16) float g_o1 [NN * 256];
__device__ __align__(16) float g_h2 [NN * 64];
__device__ __align__(16) float g_o2 [NN * 64];
__device__ __align__(16) float g_as [NN * 4];
__device__ __align__(16) float g_ad [NN * 4];
__device__ __align__(16) float g_was[256];
__device__ __align__(16) float g_wad[256];
__device__ __align__(16) float g_aoff[8];
__device__ int g_deg[NN];
__device__ int g_off[NN + 1];
__device__ int g_srcs[ETOT];
__device__ int g_epos[ETOT];

// ---------------- CSR build ----------------
__global__ void k_count(const int* __restrict__ ei) {
    int i = blockIdx.x * blockDim.x + threadIdx.x;
    if (i >= ETOT) return;
    int d = (i < NE) ? ei[NE + i] : (i - NE);
    g_epos[i] = atomicAdd(&g_deg[d], 1);
}

// scan: each block re-sums preceding degrees for its base, then local scan
__global__ void k_swrite() {
    __shared__ int sh[1024];
    int t = threadIdx.x;
    int b = blockIdx.x;
    int part = 0;
    for (int i = t; i < b * 1024; i += 1024) part += g_deg[i];
    sh[t] = part;
    __syncthreads();
#pragma unroll
    for (int o = 512; o > 0; o >>= 1) {
        if (t < o) sh[t] += sh[t + o];
        __syncthreads();
    }
    int base = sh[0];
    __syncthreads();
    int i = b * 1024 + t;
    int v = (i < NN) ? g_deg[i] : 0;
    sh[t] = v;
    __syncthreads();
#pragma unroll
    for (int o = 1; o < 1024; o <<= 1) {
        int x = (t >= o) ? sh[t - o] : 0;
        __syncthreads();
        sh[t] += x;
        __syncthreads();
    }
    int incl = sh[t];
    if (i < NN) {
        g_off[i] = base + incl - v;
        if (i == NN - 1) g_off[NN] = base + incl;
    }
}

__global__ void k_scatter(const int* __restrict__ ei) {
    int i = blockIdx.x * blockDim.x + threadIdx.x;
    if (i >= ETOT) return;
    int s, d;
    if (i < NE) { s = ei[i]; d = ei[NE + i]; }
    else        { s = i - NE; d = i - NE; }
    g_srcs[g_off[d] + g_epos[i]] = s;
}

// ---------------- parallel double fold (1024 threads) ---------------------
// Stage 1: sw[k][h] = sum_c g1_w[k*256+h*64+c]*a{s,d}[h*64+c]
// Stage 2: g_was[k*4+h] = sum_o enc_w2[k*64+o]*sw[o][h]; aoff = b2 . sw/sd
// 4 threads per output, each sums 16 elements (float4), shfl-combined.
__global__ void k_fold1b(const float* __restrict__ w, const float* __restrict__ as_,
                         const float* __restrict__ ad_, const float* __restrict__ w2,
                         const float* __restrict__ b2) {
    __shared__ float sw[64][4], sd[64][4];
    int t = threadIdx.x;          // 1024
    int out = t >> 2, p = t & 3;  // out = k*4 + h
    int k = out >> 2, h = out & 3;
    {
        const float4* wr = (const float4*)(w + k * 256 + h * 64) + p * 4;
        const float4* ar = (const float4*)(as_ + h * 64) + p * 4;
        const float4* dr = (const float4*)(ad_ + h * 64) + p * 4;
        float s = 0.f, d = 0.f;
#pragma unroll
        for (int q = 0; q < 4; q++) {
            float4 wv = wr[q], av = ar[q], dv = dr[q];
            s += wv.x * av.x + wv.y * av.y + wv.z * av.z + wv.w * av.w;
            d += wv.x * dv.x + wv.y * dv.y + wv.z * dv.z + wv.w * dv.w;
        }
        s += __shfl_xor_sync(0xffffffffu, s, 1);
        s += __shfl_xor_sync(0xffffffffu, s, 2);
        d += __shfl_xor_sync(0xffffffffu, d, 1);
        d += __shfl_xor_sync(0xffffffffu, d, 2);
        if (p == 0) { sw[k][h] = s; sd[k][h] = d; }
    }
    __syncthreads();
    {
        float s2 = 0.f, d2 = 0.f;
#pragma unroll
        for (int q = 0; q < 16; q++) {
            int o = p * 16 + q;
            float v = w2[k * 64 + o];
            s2 += v * sw[o][h];
            d2 += v * sd[o][h];
        }
        s2 += __shfl_xor_sync(0xffffffffu, s2, 1);
        s2 += __shfl_xor_sync(0xffffffffu, s2, 2);
        d2 += __shfl_xor_sync(0xffffffffu, d2, 1);
        d2 += __shfl_xor_sync(0xffffffffu, d2, 2);
        if (p == 0) { g_was[out] = s2; g_wad[out] = d2; }
    }
    if (t < 8) {
        int hh = t & 3;
        float acc = 0.f;
#pragma unroll
        for (int o = 0; o < 64; o++)
            acc += b2[o] * (t >= 4 ? sd[o][hh] : sw[o][hh]);
        g_aoff[t] = acc;
    }
}

// ---------------- fused encoder layer 1 + alpha1 (warp per node) ----------
// Lanes compute mid[n][lane], mid[n][lane+32] (K=7 dots, relu), store mid,
// then the 8 alpha dots via the double-folded weights + warp reduce.
__global__ void k_enc1a(const float* __restrict__ x, const float* __restrict__ w1,
                        const float* __restrict__ b1) {
    int warp = (blockIdx.x * blockDim.x + threadIdx.x) >> 5;
    int lane = threadIdx.x & 31;
    if (warp >= NN) return;
    float m1 = b1[lane], m2 = b1[lane + 32];
#pragma unroll
    for (int k = 0; k < 7; k++) {
        float xv = x[warp * 7 + k];
        m1 += xv * w1[k * 64 + lane];
        m2 += xv * w1[k * 64 + lane + 32];
    }
    m1 = fmaxf(m1, 0.f);
    m2 = fmaxf(m2, 0.f);
    g_mid[(size_t)warp * 64 + lane]      = m1;
    g_mid[(size_t)warp * 64 + lane + 32] = m2;

    float4 wsA = ((const float4*)g_was)[lane];
    float4 wsB = ((const float4*)g_was)[lane + 32];
    float4 wdA = ((const float4*)g_wad)[lane];
    float4 wdB = ((const float4*)g_wad)[lane + 32];
    float4 ps, pd;
    ps.x = m1 * wsA.x + m2 * wsB.x; ps.y = m1 * wsA.y + m2 * wsB.y;
    ps.z = m1 * wsA.z + m2 * wsB.z; ps.w = m1 * wsA.w + m2 * wsB.w;
    pd.x = m1 * wdA.x + m2 * wdB.x; pd.y = m1 * wdA.y + m2 * wdB.y;
    pd.z = m1 * wdA.z + m2 * wdB.z; pd.w = m1 * wdA.w + m2 * wdB.w;
#pragma unroll
    for (int o = 16; o; o >>= 1) {
        ps.x += __shfl_xor_sync(0xffffffffu, ps.x, o);
        ps.y += __shfl_xor_sync(0xffffffffu, ps.y, o);
        ps.z += __shfl_xor_sync(0xffffffffu, ps.z, o);
        ps.w += __shfl_xor_sync(0xffffffffu, ps.w, o);
        pd.x += __shfl_xor_sync(0xffffffffu, pd.x, o);
        pd.y += __shfl_xor_sync(0xffffffffu, pd.y, o);
        pd.z += __shfl_xor_sync(0xffffffffu, pd.z, o);
        pd.w += __shfl_xor_sync(0xffffffffu, pd.w, o);
    }
    if (lane == 0) {
        float4 os = ((const float4*)g_aoff)[0];
        float4 od = ((const float4*)g_aoff)[1];
        ps.x += os.x; ps.y += os.y; ps.z += os.z; ps.w += os.w;
        pd.x += od.x; pd.y += od.y; pd.z += od.z; pd.w += od.w;
        ((float4*)g_as)[warp] = ps;
        ((float4*)g_ad)[warp] = pd;
    }
}

// ---------------- tf32 tensor-core GEMM (2xTF32: exact A, tf32 B) ---------
__device__ __forceinline__ float tf32_rn(float x) {
    uint32_t u;
    asm("cvt.rna.tf32.f32 %0, %1;" : "=r"(u) : "f"(x));
    return __uint_as_float(u);
}

__device__ __forceinline__ void mma_tf32(float4& d, const uint32_t a[4], const uint32_t b[2]) {
    asm volatile(
        "mma.sync.aligned.m16n8k8.row.col.f32.tf32.tf32.f32 "
        "{%0,%1,%2,%3},{%4,%5,%6,%7},{%8,%9},{%0,%1,%2,%3};\n"
        : "+f"(d.x), "+f"(d.y), "+f"(d.z), "+f"(d.w)
        : "r"(a[0]), "r"(a[1]), "r"(a[2]), "r"(a[3]), "r"(b[0]), "r"(b[1]));
}

// ACT: 0 none, 1 relu, 2 elu
// EPI: 0 normal store
//      1 store C AND compute layer-2 alphas from the 128x64 tile (axA=as, axB=ad)
//      2 decoder: relu tile, NO C store; out[r,0:4] = tile @ axA(64x4) + axB(4); axO=out
template <int ACT, int EPI>
__global__ void k_mma_gemm(const float* __restrict__ A, const float* __restrict__ B,
                           const float* __restrict__ bias, float* __restrict__ C,
                           int M, int K, int Nc, int lda, int ldb, int ldc, int zoff,
                           const float* __restrict__ axA, const float* __restrict__ axB,
                           float* __restrict__ axO) {
    __shared__ __align__(16) float smbuf[8192];
    float (*Ah)[136] = (float(*)[136])(smbuf);
    float (*Al)[136] = (float(*)[136])(smbuf + 16 * 136);
    float (*Bh)[72]  = (float(*)[72]) (smbuf + 2 * 16 * 136);
    float* scratch   = smbuf;

    int zo = blockIdx.z * zoff;
    A += zo; B += zo;
    if (C) C += zo;
    if (bias) bias += zo;

    int tid  = threadIdx.x;
    int warp = tid >> 5, lane = tid & 31;
    int wm = warp >> 1, wn = warp & 1;
    int m0 = blockIdx.y * 128, n0 = blockIdx.x * 64;
    int grp = lane >> 2, tig = lane & 3;

    float4 acc[2][4];
#pragma unroll
    for (int i = 0; i < 2; i++)
#pragma unroll
        for (int j = 0; j < 4; j++) acc[i][j] = make_float4(0.f, 0.f, 0.f, 0.f);

    for (int k0 = 0; k0 < K; k0 += 16) {
#pragma unroll
        for (int r = 0; r < 2; r++) {
            int idx = tid + 256 * r;
            int m = idx >> 2, kq = idx & 3;
            int row = m0 + m;
            float4 v = make_float4(0.f, 0.f, 0.f, 0.f);
            if (row < M) v = *(const float4*)(A + (size_t)row * lda + k0 + 4 * kq);
            float h;
            h = tf32_rn(v.x); Ah[4*kq+0][m] = h; Al[4*kq+0][m] = tf32_rn(v.x - h);
            h = tf32_rn(v.y); Ah[4*kq+1][m] = h; Al[4*kq+1][m] = tf32_rn(v.y - h);
            h = tf32_rn(v.z); Ah[4*kq+2][m] = h; Al[4*kq+2][m] = tf32_rn(v.z - h);
            h = tf32_rn(v.w); Ah[4*kq+3][m] = h; Al[4*kq+3][m] = tf32_rn(v.w - h);
        }
        {
            int kk = tid >> 4, nq = tid & 15;
            float4 v = *(const float4*)(B + (size_t)(k0 + kk) * ldb + n0 + 4 * nq);
            float4 hv;
            hv.x = tf32_rn(v.x);
            hv.y = tf32_rn(v.y);
            hv.z = tf32_rn(v.z);
            hv.w = tf32_rn(v.w);
            *(float4*)&Bh[kk][4 * nq] = hv;
        }
        __syncthreads();

#pragma unroll
        for (int ks = 0; ks < 2; ks++) {
            int kb = ks * 8;
            uint32_t aH[2][4], aL[2][4];
#pragma unroll
            for (int mt = 0; mt < 2; mt++) {
                int mb = wm * 32 + mt * 16 + grp;
                aH[mt][0] = __float_as_uint(Ah[kb + tig    ][mb]);
                aH[mt][1] = __float_as_uint(Ah[kb + tig    ][mb + 8]);
                aH[mt][2] = __float_as_uint(Ah[kb + tig + 4][mb]);
                aH[mt][3] = __float_as_uint(Ah[kb + tig + 4][mb + 8]);
                aL[mt][0] = __float_as_uint(Al[kb + tig    ][mb]);
                aL[mt][1] = __float_as_uint(Al[kb + tig    ][mb + 8]);
                aL[mt][2] = __float_as_uint(Al[kb + tig + 4][mb]);
                aL[mt][3] = __float_as_uint(Al[kb + tig + 4][mb + 8]);
            }
#pragma unroll
            for (int nt = 0; nt < 4; nt++) {
                int nb = wn * 32 + nt * 8 + grp;
                uint32_t bH[2];
                bH[0] = __float_as_uint(Bh[kb + tig    ][nb]);
                bH[1] = __float_as_uint(Bh[kb + tig + 4][nb]);
#pragma unroll
                for (int mt = 0; mt < 2; mt++) {
                    mma_tf32(acc[mt][nt], aH[mt], bH);
                    mma_tf32(acc[mt][nt], aL[mt], bH);
                }
            }
        }
        __syncthreads();
    }

#pragma unroll
    for (int mt = 0; mt < 2; mt++) {
#pragma unroll
        for (int nt = 0; nt < 4; nt++) {
            int lc  = wn * 32 + nt * 8 + 2 * tig;
            int col = n0 + lc;
            float b0 = bias ? bias[col] : 0.f;
            float b1 = bias ? bias[col + 1] : 0.f;
            int lr  = wm * 32 + mt * 16 + grp;
            int rt_ = m0 + lr;
            float2 v0 = make_float2(acc[mt][nt].x + b0, acc[mt][nt].y + b1);
            float2 v1 = make_float2(acc[mt][nt].z + b0, acc[mt][nt].w + b1);
            if (ACT == 1) {
                v0.x = fmaxf(v0.x, 0.f); v0.y = fmaxf(v0.y, 0.f);
                v1.x = fmaxf(v1.x, 0.f); v1.y = fmaxf(v1.y, 0.f);
            } else if (ACT == 2) {
                v0.x = v0.x > 0.f ? v0.x : expm1f(v0.x);
                v0.y = v0.y > 0.f ? v0.y : expm1f(v0.y);
                v1.x = v1.x > 0.f ? v1.x : expm1f(v1.x);
                v1.y = v1.y > 0.f ? v1.y : expm1f(v1.y);
            }
            if (EPI != 2) {
                if (rt_ < M)     *(float2*)(C + (size_t)rt_ * ldc + col)       = v0;
                if (rt_ + 8 < M) *(float2*)(C + (size_t)(rt_ + 8) * ldc + col) = v1;
            }
            if (EPI != 0) {
                scratch[lr * 64 + lc]           = v0.x;
                scratch[lr * 64 + lc + 1]       = v0.y;
                scratch[(lr + 8) * 64 + lc]     = v1.x;
                scratch[(lr + 8) * 64 + lc + 1] = v1.y;
            }
        }
    }

    if (EPI == 1) {   // fused layer-2 alpha
        __syncthreads();
        float a0 = axA[2 * lane], a1 = axA[2 * lane + 1];
        float d0 = axB[2 * lane], d1 = axB[2 * lane + 1];
        int h = lane >> 3;
#pragma unroll 4
        for (int r = warp * 16; r < warp * 16 + 16; r++) {
            float u0 = scratch[r * 64 + 2 * lane];
            float u1 = scratch[r * 64 + 2 * lane + 1];
            float s  = u0 * a0 + u1 * a1;
            float dd = u0 * d0 + u1 * d1;
#pragma unroll
            for (int o = 4; o; o >>= 1) {
                s  += __shfl_xor_sync(0xffffffffu, s,  o);
                dd += __shfl_xor_sync(0xffffffffu, dd, o);
            }
            int grow = m0 + r;
            if ((lane & 7) == 0 && grow < M) {
                g_as[grow * 4 + h] = s;
                g_ad[grow * 4 + h] = dd;
            }
        }
    } else if (EPI == 2) {  // fused decoder tail
        __syncthreads();
        float4 wa = ((const float4*)axA)[2 * lane];
        float4 wb = ((const float4*)axA)[2 * lane + 1];
        float4 bb = *(const float4*)axB;
#pragma unroll 4
        for (int r = warp * 16; r < warp * 16 + 16; r++) {
            float u0 = scratch[r * 64 + 2 * lane];
            float u1 = scratch[r * 64 + 2 * lane + 1];
            float4 o;
            o.x = u0 * wa.x + u1 * wb.x;
            o.y = u0 * wa.y + u1 * wb.y;
            o.z = u0 * wa.z + u1 * wb.z;
            o.w = u0 * wa.w + u1 * wb.w;
#pragma unroll
            for (int of = 16; of; of >>= 1) {
                o.x += __shfl_xor_sync(0xffffffffu, o.x, of);
                o.y += __shfl_xor_sync(0xffffffffu, o.y, of);
                o.z += __shfl_xor_sync(0xffffffffu, o.z, of);
                o.w += __shfl_xor_sync(0xffffffffu, o.w, of);
            }
            int grow = m0 + r;
            if (lane == 0 && grow < M) {
                ((float4*)axO)[grow] = make_float4(o.x + bb.x, o.y + bb.y,
                                                   o.z + bb.z, o.w + bb.w);
            }
        }
    }
}

__device__ __forceinline__ float lrelu(float e) { return e > 0.f ? e : NEG * e; }

// ---------------- layer-1 aggregate, half-warp edge-split -----------------
__global__ void k_agg1(const float* __restrict__ h0f, float* __restrict__ aggout) {
    __shared__ float4 sh_w[8][32];
    __shared__ int    sh_s[8][32];
    int warp = (blockIdx.x * blockDim.x + threadIdx.x) >> 5;
    int lane = threadIdx.x & 31;
    if (warp >= NN) return;
    int wip = threadIdx.x >> 5;
    int half = lane >> 4, sub = lane & 15;
    int d = warp;
    int r0 = g_off[d], deg = g_off[d + 1] - r0;
    float4 adv = ((const float4*)g_ad)[d];

    float4 A0 = make_float4(0.f,0.f,0.f,0.f), A1 = A0, A2 = A0, A3 = A0;
    float s0 = 0.f, s1 = 0.f, s2 = 0.f, s3 = 0.f;

    for (int base = 0; base < deg; base += 32) {
        int n = deg - base; if (n > 32) n = 32;
        float4 w = make_float4(0.f, 0.f, 0.f, 0.f); int s = 0;
        if (lane < n) {
            s = g_srcs[r0 + base + lane];
            float4 a = ((const float4*)g_as)[s];
            w.x = __expf(lrelu(a.x + adv.x));
            w.y = __expf(lrelu(a.y + adv.y));
            w.z = __expf(lrelu(a.z + adv.z));
            w.w = __expf(lrelu(a.w + adv.w));
        }
        s0 += w.x; s1 += w.y; s2 += w.z; s3 += w.w;
        sh_w[wip][lane] = w;
        sh_s[wip][lane] = s;
        __syncwarp();
#pragma unroll 4
        for (int j = half; j < n; j += 2) {
            float4 wv = sh_w[wip][j];
            int sj = sh_s[wip][j];
            float4 v = *(const float4*)(h0f + (size_t)sj * 64 + sub * 4);
            A0.x += v.x*wv.x; A0.y += v.y*wv.x; A0.z += v.z*wv.x; A0.w += v.w*wv.x;
            A1.x += v.x*wv.y; A1.y += v.y*wv.y; A1.z += v.z*wv.y; A1.w += v.w*wv.y;
            A2.x += v.x*wv.z; A2.y += v.y*wv.z; A2.z += v.z*wv.z; A2.w += v.w*wv.z;
            A3.x += v.x*wv.w; A3.y += v.y*wv.w; A3.z += v.z*wv.w; A3.w += v.w*wv.w;
        }
        __syncwarp();
    }
    A0.x += __shfl_xor_sync(0xffffffffu, A0.x, 16);
    A0.y += __shfl_xor_sync(0xffffffffu, A0.y, 16);
    A0.z += __shfl_xor_sync(0xffffffffu, A0.z, 16);
    A0.w += __shfl_xor_sync(0xffffffffu, A0.w, 16);
    A1.x += __shfl_xor_sync(0xffffffffu, A1.x, 16);
    A1.y += __shfl_xor_sync(0xffffffffu, A1.y, 16);
    A1.z += __shfl_xor_sync(0xffffffffu, A1.z, 16);
    A1.w += __shfl_xor_sync(0xffffffffu, A1.w, 16);
    A2.x += __shfl_xor_sync(0xffffffffu, A2.x, 16);
    A2.y += __shfl_xor_sync(0xffffffffu, A2.y, 16);
    A2.z += __shfl_xor_sync(0xffffffffu, A2.z, 16);
    A2.w += __shfl_xor_sync(0xffffffffu, A2.w, 16);
    A3.x += __shfl_xor_sync(0xffffffffu, A3.x, 16);
    A3.y += __shfl_xor_sync(0xffffffffu, A3.y, 16);
    A3.z += __shfl_xor_sync(0xffffffffu, A3.z, 16);
    A3.w += __shfl_xor_sync(0xffffffffu, A3.w, 16);
#pragma unroll
    for (int o = 16; o; o >>= 1) {
        s0 += __shfl_xor_sync(0xffffffffu, s0, o);
        s1 += __shfl_xor_sync(0xffffffffu, s1, o);
        s2 += __shfl_xor_sync(0xffffffffu, s2, o);
        s3 += __shfl_xor_sync(0xffffffffu, s3, o);
    }
    float i0 = 1.f / (s0 + EPSV), i1 = 1.f / (s1 + EPSV);
    float i2 = 1.f / (s2 + EPSV), i3 = 1.f / (s3 + EPSV);
    float* ob = aggout + (size_t)d * 256 + sub * 4;
    if (half == 0) {
        *(float4*)(ob)      = make_float4(A0.x*i0, A0.y*i0, A0.z*i0, A0.w*i0);
        *(float4*)(ob + 64) = make_float4(A1.x*i1, A1.y*i1, A1.z*i1, A1.w*i1);
    } else {
        *(float4*)(ob + 128) = make_float4(A2.x*i2, A2.y*i2, A2.z*i2, A2.w*i2);
        *(float4*)(ob + 192) = make_float4(A3.x*i3, A3.y*i3, A3.z*i3, A3.w*i3);
    }
}

// ---------------- layer-2 aggregate, half-warp edge-split -----------------
__global__ void k_agg2(const float* __restrict__ hfeat, const float* __restrict__ bias,
                       float* __restrict__ out) {
    __shared__ float4 sh_w[8][32];
    __shared__ int    sh_s[8][32];
    int warp = (blockIdx.x * blockDim.x + threadIdx.x) >> 5;
    int lane = threadIdx.x & 31;
    if (warp >= NN) return;
    int wip = threadIdx.x >> 5;
    int half = lane >> 4, sub = lane & 15;
    int headq = sub >> 2;
    int d = warp;
    int r0 = g_off[d], deg = g_off[d + 1] - r0;
    float4 adv = ((const float4*)g_ad)[d];

    float4 acc = make_float4(0.f, 0.f, 0.f, 0.f);
    float s0 = 0.f, s1 = 0.f, s2 = 0.f, s3 = 0.f;
    for (int base = 0; base < deg; base += 32) {
        int n = deg - base; if (n > 32) n = 32;
        float4 w = make_float4(0.f, 0.f, 0.f, 0.f); int s = 0;
        if (lane < n) {
            s = g_srcs[r0 + base + lane];
            float4 a = ((const float4*)g_as)[s];
            w.x = __expf(lrelu(a.x + adv.x));
            w.y = __expf(lrelu(a.y + adv.y));
            w.z = __expf(lrelu(a.z + adv.z));
            w.w = __expf(lrelu(a.w + adv.w));
        }
        s0 += w.x; s1 += w.y; s2 += w.z; s3 += w.w;
        sh_w[wip][lane] = w;
        sh_s[wip][lane] = s;
        __syncwarp();
#pragma unroll 4
        for (int j = half; j < n; j += 2) {
            float4 wv = sh_w[wip][j];
            int sj = sh_s[wip][j];
            float wm = headq == 0 ? wv.x : headq == 1 ? wv.y : headq == 2 ? wv.z : wv.w;
            float4 v = *(const float4*)(hfeat + (size_t)sj * 64 + sub * 4);
            acc.x += v.x * wm; acc.y += v.y * wm;
            acc.z += v.z * wm; acc.w += v.w * wm;
        }
        __syncwarp();
    }
    acc.x += __shfl_xor_sync(0xffffffffu, acc.x, 16);
    acc.y += __shfl_xor_sync(0xffffffffu, acc.y, 16);
    acc.z += __shfl_xor_sync(0xffffffffu, acc.z, 16);
    acc.w += __shfl_xor_sync(0xffffffffu, acc.w, 16);
#pragma unroll
    for (int o = 16; o; o >>= 1) {
        s0 += __shfl_xor_sync(0xffffffffu, s0, o);
        s1 += __shfl_xor_sync(0xffffffffu, s1, o);
        s2 += __shfl_xor_sync(0xffffffffu, s2, o);
        s3 += __shfl_xor_sync(0xffffffffu, s3, o);
    }
    if (half == 0) {
        float im = headq == 0 ? 1.f / (s0 + EPSV) : headq == 1 ? 1.f / (s1 + EPSV)
                 : headq == 2 ? 1.f / (s2 + EPSV) : 1.f / (s3 + EPSV);
        float4 bv = ((const float4*)bias)[sub];
        float4 r;
        r.x = acc.x * im + bv.x;
        r.y = acc.y * im + bv.y;
        r.z = acc.z * im + bv.z;
        r.w = acc.w * im + bv.w;
        ((float4*)(out + (size_t)d * 64))[sub] = r;
    }
}

// ---------------- launch ----------------
extern "C" void kernel_launch(void* const* d_in, const int* in_sizes, int n_in,
                              void* d_out, int out_size) {
    const float* x      = (const float*)d_in[0];
    const int*   ei     = (const int*)  d_in[1];
    const float* enc_w1 = (const float*)d_in[2];
    const float* enc_b1 = (const float*)d_in[3];
    const float* enc_w2 = (const float*)d_in[4];
    const float* enc_b2 = (const float*)d_in[5];
    const float* g1_w   = (const float*)d_in[6];
    const float* g1_as  = (const float*)d_in[7];
    const float* g1_ad  = (const float*)d_in[8];
    const float* g1_b   = (const float*)d_in[9];
    const float* g2_w   = (const float*)d_in[10];
    const float* g2_as  = (const float*)d_in[11];
    const float* g2_ad  = (const float*)d_in[12];
    const float* g2_b   = (const float*)d_in[13];
    const float* dec_w1 = (const float*)d_in[14];
    const float* dec_b1 = (const float*)d_in[15];
    const float* dec_w2 = (const float*)d_in[16];
    const float* dec_b2 = (const float*)d_in[17];
    float* out = (float*)d_out;

    float *mid, *h0, *agg, *o1, *h2, *o2;
    cudaGetSymbolAddress((void**)&mid, g_mid);
    cudaGetSymbolAddress((void**)&h0,  g_h0);
    cudaGetSymbolAddress((void**)&agg, g_agg);
    cudaGetSymbolAddress((void**)&o1,  g_o1);
    cudaGetSymbolAddress((void**)&h2,  g_h2);
    cudaGetSymbolAddress((void**)&o2,  g_o2);
    void* degp;
    cudaGetSymbolAddress(&degp, g_deg);

    static cudaStream_t s1 = 0;
    static cudaEvent_t evRoot = 0, evCSR = 0;
    static int inited = 0;
    if (!inited) {
        cudaStreamCreateWithFlags(&s1, cudaStreamNonBlocking);
        cudaEventCreateWithFlags(&evRoot, cudaEventDisableTiming);
        cudaEventCreateWithFlags(&evCSR,  cudaEventDisableTiming);
        inited = 1;
    }

    const int WPB = 6250;      // 50000 warps / 8 warps-per-block
    const int GY  = (NN + 127) / 128;

    // ---- fork ----
    cudaEventRecord(evRoot, 0);
    cudaStreamWaitEvent(s1, evRoot, 0);

    // branch s1: CSR build
    cudaMemsetAsync(degp, 0, NN * sizeof(int), s1);
    k_count<<<(ETOT + 255) / 256, 256, 0, s1>>>(ei);
    k_swrite<<<NB1, 1024, 0, s1>>>();
    k_scatter<<<(ETOT + 255) / 256, 256, 0, s1>>>(ei);
    cudaEventRecord(evCSR, s1);

    // main: fold -> fused encoder+alpha1 -> enc GEMM
    k_fold1b<<<1, 1024>>>(g1_w, g1_as, g1_ad, enc_w2, enc_b2);
    k_enc1a<<<WPB, 256>>>(x, enc_w1, enc_b1);
    k_mma_gemm<0, 0><<<dim3(1, GY), 256>>>(mid, enc_w2, enc_b2, h0,
                                           NN, 64, 64, 64, 64, 64, 0,
                                           nullptr, nullptr, nullptr);

    // ---- join: aggregation needs CSR + alphas + h0 ----
    cudaStreamWaitEvent(0, evCSR, 0);
    k_agg1<<<WPB, 256>>>(h0, agg);
    k_mma_gemm<2, 0><<<dim3(1, GY, 4), 256>>>(agg, g1_w, g1_b, o1,
                                              NN, 64, 64, 256, 256, 256, 64,
                                              nullptr, nullptr, nullptr);

    // GAT layer 2 weight GEMM with fused alpha2 epilogue
    k_mma_gemm<0, 1><<<dim3(1, GY), 256>>>(o1, g2_w, nullptr, h2,
                                           NN, 256, 64, 256, 64, 64, 0,
                                           g2_as, g2_ad, nullptr);
    k_agg2<<<WPB, 256>>>(h2, g2_b, o2);

    // decoder: one GEMM with fused final-layer epilogue (writes out directly)
    k_mma_gemm<1, 2><<<dim3(1, GY), 256>>>(o2, dec_w1, dec_b1, nullptr,
                                           NN, 64, 64, 64, 64, 64, 0,
                                           dec_w2, dec_b2, out);
}